// round 13
// baseline (speedup 1.0000x reference)
#include <cuda_runtime.h>
#include <cuda_bf16.h>
#include <math.h>
#include <stdint.h>

#define BB 2
#define SSEQ 2048
#define DD 1024
#define HH 16
#define HD 64
#define FF 4096
#define NL 8
#define NT (BB*SSEQ)

// ---------------- scratch ----------------
__device__ float g_x[NT*DD];
__device__ float g_f[NT*FF];
__device__ unsigned g_fmax[NT];
__device__ int8_t g_h8h[NT*DD];
__device__ int8_t g_h8l[NT*DD];
__device__ float  g_sh[NT];
__device__ int8_t g_f8h[NT*FF];
__device__ int8_t g_f8l[NT*FF];
__device__ float  g_sf[NT];
__device__ __nv_bfloat16 g_q_hi[NT*DD];
__device__ __nv_bfloat16 g_q_lo[NT*DD];
__device__ __nv_bfloat16 g_kv_hi[NT*2*DD];
__device__ __nv_bfloat16 g_kv_lo[NT*2*DD];
__device__ __nv_bfloat16 g_att_hi[NT*DD];
__device__ __nv_bfloat16 g_att_lo[NT*DD];
// int8 weights [out][in] + per-out scales; max-bits arrays (zero-init, idempotent)
__device__ int8_t g_wqkv8h[NL*3*DD*DD];
__device__ int8_t g_wqkv8l[NL*3*DD*DD];
__device__ float  g_swqkv[NL*3*DD];
__device__ unsigned g_mxqkv[NL*3*DD];
__device__ int8_t g_w18h[NL*FF*DD];
__device__ int8_t g_w18l[NL*FF*DD];
__device__ float  g_sw1[NL*FF];
__device__ unsigned g_mxw1[NL*FF];
__device__ int8_t g_w28h[NL*DD*FF];
__device__ int8_t g_w28l[NL*DD*FF];
__device__ float  g_sw2[NL*DD];
__device__ unsigned g_mxw2[NL*DD];
__device__ __nv_bfloat16 g_wo_h[NL*DD*DD];
__device__ __nv_bfloat16 g_wo_l[NL*DD*DD];

// ---------------- helpers ----------------
__device__ __forceinline__ float softplus_f(float x) {
    return fmaxf(x, 0.0f) + log1pf(expf(-fabsf(x)));
}
__device__ __forceinline__ uint32_t smem_u32(const void* p) {
    uint32_t a;
    asm("{ .reg .u64 t; cvta.to.shared.u64 t, %1; cvt.u32.u64 %0, t; }" : "=r"(a) : "l"(p));
    return a;
}
__device__ __forceinline__ void cp16(uint32_t s, const void* g) {
    asm volatile("cp.async.cg.shared.global [%0], [%1], 16;" :: "r"(s), "l"(g));
}
#define CP_COMMIT() asm volatile("cp.async.commit_group;")
#define CP_WAIT0()  asm volatile("cp.async.wait_group 0;")
#define CP_WAIT1()  asm volatile("cp.async.wait_group 1;")
__device__ __forceinline__ void split2(float a, float b, uint32_t& hi, uint32_t& lo) {
    __nv_bfloat162 h = __floats2bfloat162_rn(a, b);
    float ra = a - __bfloat162float(h.x);
    float rb = b - __bfloat162float(h.y);
    __nv_bfloat162 l = __floats2bfloat162_rn(ra, rb);
    hi = *(uint32_t*)&h; lo = *(uint32_t*)&l;
}
__device__ __forceinline__ void quant1(float v, float inv, int& hi, int& lo) {
    int iq = __float2int_rn(v * inv);
    hi = (iq + 128) >> 8;
    lo = iq - (hi << 8);
}
#define LDMX4(R0,R1,R2,R3,ADDR) \
    asm volatile("ldmatrix.sync.aligned.m8n8.x4.shared.b16 {%0,%1,%2,%3}, [%4];" \
        : "=r"(R0),"=r"(R1),"=r"(R2),"=r"(R3) : "r"(ADDR))
#define LDMX4T(R0,R1,R2,R3,ADDR) \
    asm volatile("ldmatrix.sync.aligned.m8n8.x4.trans.shared.b16 {%0,%1,%2,%3}, [%4];" \
        : "=r"(R0),"=r"(R1),"=r"(R2),"=r"(R3) : "r"(ADDR))
#define MMA16816(C, A, B0, B1) \
    asm volatile("mma.sync.aligned.m16n8k16.row.col.f32.bf16.bf16.f32 " \
        "{%0,%1,%2,%3}, {%4,%5,%6,%7}, {%8,%9}, {%0,%1,%2,%3};" \
        : "+f"((C)[0]),"+f"((C)[1]),"+f"((C)[2]),"+f"((C)[3]) \
        : "r"((A)[0]),"r"((A)[1]),"r"((A)[2]),"r"((A)[3]), "r"(B0),"r"(B1))
#define MMAS8(C, A, B0, B1) \
    asm volatile("mma.sync.aligned.m16n8k32.row.col.s32.s8.s8.s32 " \
        "{%0,%1,%2,%3}, {%4,%5,%6,%7}, {%8,%9}, {%0,%1,%2,%3};" \
        : "+r"((C)[0]),"+r"((C)[1]),"+r"((C)[2]),"+r"((C)[3]) \
        : "r"((A)[0]),"r"((A)[1]),"r"((A)[2]),"r"((A)[3]), "r"(B0),"r"(B1))

// ---------------- weight pipeline ----------------
__global__ void wq8max_kernel(const float* __restrict__ W, unsigned* __restrict__ mx,
                              int K, int M, size_t mstride)
{
    W  += (size_t)blockIdx.z * K * M;
    mx += (size_t)blockIdx.z * mstride;
    int m = blockIdx.x * 256 + threadIdx.x;
    int kper = K >> 3, k0 = blockIdx.y * kper;
    float v = 0.0f;
    for (int k = k0; k < k0 + kper; k++) v = fmaxf(v, fabsf(W[(size_t)k * M + m]));
    atomicMax(mx + m, __float_as_uint(v));
}
__global__ void wq8fin_kernel(const unsigned* __restrict__ mx, float* __restrict__ s, int n)
{
    int i = blockIdx.x * 256 + threadIdx.x;
    if (i < n) s[i] = fmaxf(__uint_as_float(mx[i]), 1e-30f) * (1.0f / 32639.0f);
}
__global__ void wq8conv_kernel(const float* __restrict__ W,
                               int8_t* __restrict__ oh, int8_t* __restrict__ ol,
                               const float* __restrict__ sB,
                               int K, int M, size_t ostride, size_t sstride)
{
    W  += (size_t)blockIdx.z * K * M;
    oh += (size_t)blockIdx.z * ostride;
    ol += (size_t)blockIdx.z * ostride;
    sB += (size_t)blockIdx.z * sstride;
    __shared__ float t[32][33];
    int m0 = blockIdx.x * 32, k0 = blockIdx.y * 32;
    int tx = threadIdx.x, ty = threadIdx.y;
    #pragma unroll
    for (int j = 0; j < 4; j++)
        t[ty + 8*j][tx] = W[(size_t)(k0 + ty + 8*j) * M + m0 + tx];
    __syncthreads();
    #pragma unroll
    for (int j = 0; j < 4; j++) {
        int m = m0 + ty + 8*j, k = k0 + tx;
        int hi, lo;
        quant1(t[tx][ty + 8*j], 1.0f / sB[m], hi, lo);
        oh[(size_t)m * K + k] = (int8_t)hi;
        ol[(size_t)m * K + k] = (int8_t)lo;
    }
}
__global__ void wconv_kernel(const float* __restrict__ W,
                             __nv_bfloat16* __restrict__ oh, __nv_bfloat16* __restrict__ ol,
                             int K, int M)
{
    size_t loff = (size_t)blockIdx.z * K * M;
    W += loff; oh += loff; ol += loff;
    __shared__ float t[32][33];
    int m0 = blockIdx.x * 32, k0 = blockIdx.y * 32;
    int tx = threadIdx.x, ty = threadIdx.y;
    #pragma unroll
    for (int j = 0; j < 4; j++)
        t[ty + 8*j][tx] = W[(size_t)(k0 + ty + 8*j) * M + m0 + tx];
    __syncthreads();
    #pragma unroll
    for (int j = 0; j < 4; j++) {
        float v = t[tx][ty + 8*j];
        int m = m0 + ty + 8*j, k = k0 + tx;
        __nv_bfloat16 h = __float2bfloat16(v);
        oh[(size_t)m * K + k] = h;
        ol[(size_t)m * K + k] = __float2bfloat16(v - __bfloat162float(h));
    }
}

// ---------------- LayerNorms ----------------
#define LN_REDUCE() \
    _Pragma("unroll") \
    for (int o = 16; o > 0; o >>= 1) { \
        s  += __shfl_xor_sync(0xffffffffu, s,  o); \
        sq += __shfl_xor_sync(0xffffffffu, sq, o); } \
    if ((tid & 31) == 0) { sm1[tid >> 5] = s; sm2[tid >> 5] = sq; } \
    __syncthreads(); \
    if (tid < 32) { \
        s  = (tid < 8) ? sm1[tid] : 0.0f; \
        sq = (tid < 8) ? sm2[tid] : 0.0f; \
        _Pragma("unroll") \
        for (int o = 4; o > 0; o >>= 1) { \
            s  += __shfl_xor_sync(0xffffffffu, s,  o); \
            sq += __shfl_xor_sync(0xffffffffu, sq, o); } \
        if (tid == 0) { sm1[0] = s; sm2[0] = sq; } } \
    __syncthreads();

__global__ void ln_kernel(const float* __restrict__ in, const float* __restrict__ gamma,
                          const float* __restrict__ beta, float* __restrict__ out)
{
    int row = blockIdx.x, tid = threadIdx.x;
    float4 v = *(const float4*)(in + (size_t)row * DD + tid * 4);
    float s  = v.x + v.y + v.z + v.w;
    float sq = v.x*v.x + v.y*v.y + v.z*v.z + v.w*v.w;
    __shared__ float sm1[8], sm2[8];
    LN_REDUCE();
    float mean = sm1[0] * (1.0f / DD);
    float var  = sm2[0] * (1.0f / DD) - mean * mean;
    float rs   = rsqrtf(var + 1e-3f);
    float4 g  = *(const float4*)(gamma + tid * 4);
    float4 be = *(const float4*)(beta  + tid * 4);
    float4 o4;
    o4.x = (v.x - mean) * rs * g.x + be.x;
    o4.y = (v.y - mean) * rs * g.y + be.y;
    o4.z = (v.z - mean) * rs * g.z + be.z;
    o4.w = (v.w - mean) * rs * g.w + be.w;
    *(float4*)(out + (size_t)row * DD + tid * 4) = o4;
}

__global__ void ln_q8_kernel(const float* __restrict__ in, const float* __restrict__ gamma,
                             const float* __restrict__ beta,
                             int8_t* __restrict__ ohi, int8_t* __restrict__ olo,
                             float* __restrict__ sA)
{
    int row = blockIdx.x, tid = threadIdx.x;
    float4 v = *(const float4*)(in + (size_t)row * DD + tid * 4);
    float s  = v.x + v.y + v.z + v.w;
    float sq = v.x*v.x + v.y*v.y + v.z*v.z + v.w*v.w;
    __shared__ float sm1[8], sm2[8];
    LN_REDUCE();
    float mean = sm1[0] * (1.0f / DD);
    float var  = sm2[0] * (1.0f / DD) - mean * mean;
    float rs   = rsqrtf(var + 1e-3f);
    float4 g  = *(const float4*)(gamma + tid * 4);
    float4 be = *(const float4*)(beta  + tid * 4);
    float a = (v.x - mean) * rs * g.x + be.x;
    float b = (v.y - mean) * rs * g.y + be.y;
    float c = (v.z - mean) * rs * g.z + be.z;
    float d = (v.w - mean) * rs * g.w + be.w;
    float amax = fmaxf(fmaxf(fabsf(a), fabsf(b)), fmaxf(fabsf(c), fabsf(d)));
    __syncthreads();
    #pragma unroll
    for (int o = 16; o > 0; o >>= 1) amax = fmaxf(amax, __shfl_xor_sync(0xffffffffu, amax, o));
    if ((tid & 31) == 0) sm1[tid >> 5] = amax;
    __syncthreads();
    if (tid < 32) {
        amax = (tid < 8) ? sm1[tid] : 0.0f;
        #pragma unroll
        for (int o = 4; o > 0; o >>= 1) amax = fmaxf(amax, __shfl_xor_sync(0xffffffffu, amax, o));
        if (tid == 0) sm1[0] = amax;
    }
    __syncthreads();
    float bmax = fmaxf(sm1[0], 1e-30f);
    float inv  = 32639.0f / bmax;
    if (tid == 0) sA[row] = bmax * (1.0f / 32639.0f);
    int h0,l0,h1,l1,h2,l2,h3,l3;
    quant1(a, inv, h0, l0); quant1(b, inv, h1, l1);
    quant1(c, inv, h2, l2); quant1(d, inv, h3, l3);
    uint32_t ph = (uint32_t)(uint8_t)h0 | ((uint32_t)(uint8_t)h1 << 8) |
                  ((uint32_t)(uint8_t)h2 << 16) | ((uint32_t)(uint8_t)h3 << 24);
    uint32_t pl = (uint32_t)(uint8_t)l0 | ((uint32_t)(uint8_t)l1 << 8) |
                  ((uint32_t)(uint8_t)l2 << 16) | ((uint32_t)(uint8_t)l3 << 24);
    size_t off = (size_t)row * DD + tid * 4;
    *(uint32_t*)(ohi + off) = ph;
    *(uint32_t*)(olo + off) = pl;
}

__global__ void fquant_kernel(const float* __restrict__ F, const unsigned* __restrict__ fmax,
                              int8_t* __restrict__ ohi, int8_t* __restrict__ olo,
                              float* __restrict__ sF)
{
    int row = blockIdx.x, tid = threadIdx.x;
    float bmax = fmaxf(__uint_as_float(fmax[row]), 1e-30f);
    float inv = 32639.0f / bmax;
    if (tid == 0) sF[row] = bmax * (1.0f / 32639.0f);
    #pragma unroll
    for (int c = 0; c < 4; c++) {
        int col = c * 1024 + tid * 4;
        float4 v = *(const float4*)(F + (size_t)row * FF + col);
        int h0,l0,h1,l1,h2,l2,h3,l3;
        quant1(v.x, inv, h0, l0); quant1(v.y, inv, h1, l1);
        quant1(v.z, inv, h2, l2); quant1(v.w, inv, h3, l3);
        uint32_t ph = (uint32_t)(uint8_t)h0 | ((uint32_t)(uint8_t)h1 << 8) |
                      ((uint32_t)(uint8_t)h2 << 16) | ((uint32_t)(uint8_t)h3 << 24);
        uint32_t pl = (uint32_t)(uint8_t)l0 | ((uint32_t)(uint8_t)l1 << 8) |
                      ((uint32_t)(uint8_t)l2 << 16) | ((uint32_t)(uint8_t)l3 << 24);
        size_t off = (size_t)row * FF + col;
        *(uint32_t*)(ohi + off) = ph;
        *(uint32_t*)(olo + off) = pl;
    }
}

// ---------------- int8 limb GEMM, 128x64, cp.async 2-stage ----------------
// epi: 4 = QKV bf16-split outputs ; 1 = softplus -> F fp32 + rowmax ; 2 = bias+res -> fp32
#define Q_TSTR 80
#define QA_H 0
#define QA_L (128*Q_TSTR)
#define QB_H (2*128*Q_TSTR)
#define QB_L (QB_H + 64*Q_TSTR)
#define Q_STAGE (QB_L + 64*Q_TSTR)
#define Q_SMEM (2*Q_STAGE)

#define Q_LOADS(kb, stg) do {                                             \
    uint32_t base_ = sb + (uint32_t)(stg) * Q_STAGE;                      \
    _Pragma("unroll")                                                     \
    for (int u = 0; u < 2; u++) {                                         \
        int idx = tid + u * 256;                                          \
        int r = idx >> 2, c = (idx & 3) * 16;                             \
        size_t g = (size_t)(m0 + r) * K + (kb) + c;                       \
        uint32_t so = (uint32_t)(r * Q_TSTR + c);                         \
        cp16(base_ + QA_H + so, Ah + g);                                  \
        cp16(base_ + QA_L + so, Al + g);                                  \
    }                                                                     \
    {   int r = tid >> 2, c = (tid & 3) * 16;                             \
        size_t g = (size_t)(n0 + r) * K + (kb) + c;                       \
        uint32_t so = (uint32_t)(r * Q_TSTR + c);                         \
        cp16(base_ + QB_H + so, Bh + g);                                  \
        cp16(base_ + QB_L + so, Bl + g); }                                \
} while (0)

__global__ void __launch_bounds__(256) tgemm_q8(
    const int8_t* __restrict__ Ah, const int8_t* __restrict__ Al,
    const int8_t* __restrict__ Bh, const int8_t* __restrict__ Bl,
    const float* __restrict__ sA, const float* __restrict__ sB,
    const float* __restrict__ bias, const float* __restrict__ bias2,
    const float* __restrict__ res, float* __restrict__ C,
    __nv_bfloat16* __restrict__ Chi, __nv_bfloat16* __restrict__ Clo,
    __nv_bfloat16* __restrict__ Chi2, __nv_bfloat16* __restrict__ Clo2,
    float* __restrict__ F, unsigned* __restrict__ fmax,
    int K, int M, int epi)
{
    extern __shared__ char smem[];
    uint32_t sb = smem_u32(smem);
    int tid = threadIdx.x, lane = tid & 31, w = tid >> 5;
    int wm = w & 3, wn = w >> 2;
    int m0 = blockIdx.y * 128, n0 = blockIdx.x * 64;

    int acch[2][4][4], accm[2][4][4];
    #pragma unroll
    for (int i = 0; i < 2; i++)
        #pragma unroll
        for (int j = 0; j < 4; j++)
            #pragma unroll
            for (int c = 0; c < 4; c++) { acch[i][j][c] = 0; accm[i][j][c] = 0; }

    int nch = K >> 6;
    Q_LOADS(0, 0);
    CP_COMMIT();

    for (int kc = 0; kc < nch; kc++) {
        if (kc + 1 < nch) { Q_LOADS((kc + 1) * 64, (kc + 1) & 1); CP_COMMIT(); CP_WAIT1(); }
        else             { CP_WAIT0(); }
        __syncthreads();
        uint32_t stb = sb + (uint32_t)(kc & 1) * Q_STAGE;
        #pragma unroll
        for (int ks = 0; ks < 2; ks++) {
            uint32_t kb = (uint32_t)(ks * 32);
            uint32_t ah[2][4], al[2][4];
            #pragma unroll
            for (int i = 0; i < 2; i++) {
                uint32_t aa = stb + QA_H +
                    (uint32_t)((wm * 32 + i * 16 + (lane & 15)) * Q_TSTR) + kb + ((lane >> 4) << 4);
                LDMX4(ah[i][0], ah[i][1], ah[i][2], ah[i][3], aa);
                LDMX4(al[i][0], al[i][1], al[i][2], al[i][3], aa + (QA_L - QA_H));
            }
            #pragma unroll
            for (int p = 0; p < 2; p++) {
                uint32_t bh[4], bl[4];
                uint32_t ba = stb + QB_H +
                    (uint32_t)((wn * 32 + p * 16 + ((lane >> 4) << 3) + (lane & 7)) * Q_TSTR) +
                    kb + (((lane >> 3) & 1) << 4);
                LDMX4(bh[0], bh[1], bh[2], bh[3], ba);
                LDMX4(bl[0], bl[1], bl[2], bl[3], ba + (QB_L - QB_H));
                #pragma unroll
                for (int i = 0; i < 2; i++)
                    #pragma unroll
                    for (int sub = 0; sub < 2; sub++) {
                        int j = p * 2 + sub;
                        MMAS8(acch[i][j], ah[i], bh[sub * 2], bh[sub * 2 + 1]);
                        MMAS8(accm[i][j], ah[i], bl[sub * 2], bl[sub * 2 + 1]);
                        MMAS8(accm[i][j], al[i], bh[sub * 2], bh[sub * 2 + 1]);
                    }
            }
        }
        __syncthreads();
    }

    int q = lane >> 2, t2 = (lane & 3) * 2;
    bool isQ = (n0 < DD);
    #pragma unroll
    for (int i = 0; i < 2; i++) {
        int r0 = m0 + wm * 32 + i * 16 + q, r1 = r0 + 8;
        float sa0 = sA[r0], sa1 = sA[r1];
        float mx0 = 0.0f, mx1 = 0.0f;
        #pragma unroll
        for (int j = 0; j < 4; j++) {
            int col = n0 + wn * 32 + (j >> 1) * 16 + (j & 1) * 8 + t2;
            float sb0 = sB[col], sb1 = sB[col + 1];
            float v00 = sa0*sb0*(65536.0f*(float)acch[i][j][0] + 256.0f*(float)accm[i][j][0]);
            float v01 = sa0*sb1*(65536.0f*(float)acch[i][j][1] + 256.0f*(float)accm[i][j][1]);
            float v10 = sa1*sb0*(65536.0f*(float)acch[i][j][2] + 256.0f*(float)accm[i][j][2]);
            float v11 = sa1*sb1*(65536.0f*(float)acch[i][j][3] + 256.0f*(float)accm[i][j][3]);
            if (epi == 4) {
                uint32_t uh, ul;
                if (isQ) {
                    float2 b2 = *(const float2*)(bias + col);
                    v00 = (v00 + b2.x)*0.125f; v01 = (v01 + b2.y)*0.125f;
                    v10 = (v10 + b2.x)*0.125f; v11 = (v11 + b2.y)*0.125f;
                    split2(v00, v01, uh, ul);
                    *(uint32_t*)(Chi + (size_t)r0*DD + col) = uh;
                    *(uint32_t*)(Clo + (size_t)r0*DD + col) = ul;
                    split2(v10, v11, uh, ul);
                    *(uint32_t*)(Chi + (size_t)r1*DD + col) = uh;
                    *(uint32_t*)(Clo + (size_t)r1*DD + col) = ul;
                } else {
                    int ck = col - DD;
                    float2 b2 = *(const float2*)(bias2 + ck);
                    v00 += b2.x; v01 += b2.y; v10 += b2.x; v11 += b2.y;
                    split2(v00, v01, uh, ul);
                    *(uint32_t*)(Chi2 + (size_t)r0*(2*DD) + ck) = uh;
                    *(uint32_t*)(Clo2 + (size_t)r0*(2*DD) + ck) = ul;
                    split2(v10, v11, uh, ul);
                    *(uint32_t*)(Chi2 + (size_t)r1*(2*DD) + ck) = uh;
                    *(uint32_t*)(Clo2 + (size_t)r1*(2*DD) + ck) = ul;
                }
            } else if (epi == 1) {
                float2 b2 = *(const float2*)(bias + col);
                v00 = softplus_f(v00 + b2.x); v01 = softplus_f(v01 + b2.y);
                v10 = softplus_f(v10 + b2.x); v11 = softplus_f(v11 + b2.y);
                float2 f0 = {v00, v01}, f1 = {v10, v11};
                *(float2*)(F + (size_t)r0 * M + col) = f0;
                *(float2*)(F + (size_t)r1 * M + col) = f1;
                mx0 = fmaxf(mx0, fmaxf(v00, v01));
                mx1 = fmaxf(mx1, fmaxf(v10, v11));
            } else {
                float2 b2 = *(const float2*)(bias + col);
                size_t o0 = (size_t)r0 * M + col, o1 = (size_t)r1 * M + col;
                float2 rr0 = *(const float2*)(res + o0);
                float2 rr1 = *(const float2*)(res + o1);
                float2 w0 = {v00 + b2.x + rr0.x, v01 + b2.y + rr0.y};
                float2 w1 = {v10 + b2.x + rr1.x, v11 + b2.y + rr1.y};
                *(float2*)(C + o0) = w0;
                *(float2*)(C + o1) = w1;
            }
        }
        if (epi == 1) {
            atomicMax(fmax + r0, __float_as_uint(mx0));
            atomicMax(fmax + r1, __float_as_uint(mx1));
        }
    }
}

// ---------------- bf16 split GEMM (WO only, epi = bias+res) ----------------
#define TSTR 72
#define SA_H 0
#define SA_L 18432
#define SB_H 36864
#define SB_L 55296
#define TG_STAGE 73728
#define TG_SMEM (2*TG_STAGE)

#define TG_LOADS(kb, stg) do {                                            \
    uint32_t base_ = sb + (uint32_t)(stg) * TG_STAGE;                     \
    _Pragma("unroll")                                                     \
    for (int u = 0; u < 4; u++) {                                         \
        int idx = tid + u * 256;                                          \
        int r = idx >> 3, c = (idx & 7) * 8;                              \
        size_t g = (size_t)(m0 + r) * K + (kb) + c;                       \
        uint32_t so = (uint32_t)(r * TSTR + c) * 2;                       \
        cp16(base_ + SA_H + so, Ah + g);                                  \
        cp16(base_ + SA_L + so, Al + g);                                  \
        size_t gb = (size_t)(n0 + r) * K + (kb) + c;                      \
        cp16(base_ + SB_H + so, Bh + gb);                                 \
        cp16(base_ + SB_L + so, Bl + gb);                                 \
    }                                                                     \
} while (0)

__global__ void __launch_bounds__(256) tgemm_bf16(
    const __nv_bfloat16* __restrict__ Ah, const __nv_bfloat16* __restrict__ Al,
    const __nv_bfloat16* __restrict__ Bh, const __nv_bfloat16* __restrict__ Bl,
    const float* __restrict__ bias, const float* __restrict__ res,
    float* __restrict__ C, int K, int M)
{
    extern __shared__ char smem[];
    uint32_t sb = smem_u32(smem);
    int tid = threadIdx.x, lane = tid & 31, w = tid >> 5;
    int wm = w & 3, wn = w >> 2;
    int m0 = blockIdx.y * 128, n0 = blockIdx.x * 128;

    float acc[2][8][4];
    #pragma unroll
    for (int i = 0; i < 2; i++)
        #pragma unroll
        for (int j = 0; j < 8; j++)
            #pragma unroll
            for (int c = 0; c < 4; c++) acc[i][j][c] = 0.0f;

    uint32_t a_off = (uint32_t)((wm*32 + (lane & 15))*TSTR + ((lane >> 4) << 3)) * 2;
    uint32_t b_off = (uint32_t)((wn*64 + ((lane >> 4) << 3) + (lane & 7))*TSTR
                                + (((lane >> 3) & 1) << 3)) * 2;
    int nch = K >> 6;
    TG_LOADS(0, 0);
    CP_COMMIT();
    for (int kc = 0; kc < nch; kc++) {
        if (kc + 1 < nch) { TG_LOADS((kc + 1)*64, (kc + 1) & 1); CP_COMMIT(); CP_WAIT1(); }
        else             { CP_WAIT0(); }
        __syncthreads();
        uint32_t stb = sb + (uint32_t)(kc & 1) * TG_STAGE;
        #pragma unroll
        for (int ks = 0; ks < 4; ks++) {
            uint32_t kb = (uint32_t)(ks * 16) * 2;
            uint32_t ah[2][4], al[2][4];
            #pragma unroll
            for (int i = 0; i < 2; i++) {
                uint32_t aa = stb + SA_H + a_off + (uint32_t)(i*16*TSTR)*2 + kb;
                LDMX4(ah[i][0], ah[i][1], ah[i][2], ah[i][3], aa);
                LDMX4(al[i][0], al[i][1], al[i][2], al[i][3], aa + (SA_L - SA_H));
            }
            #pragma unroll
            for (int p = 0; p < 4; p++) {
                uint32_t bh[4], bl[4];
                uint32_t ba = stb + SB_H + b_off + (uint32_t)(p*16*TSTR)*2 + kb;
                LDMX4(bh[0], bh[1], bh[2], bh[3], ba);
                LDMX4(bl[0], bl[1], bl[2], bl[3], ba + (SB_L - SB_H));
                #pragma unroll
                for (int i = 0; i < 2; i++)
                    #pragma unroll
                    for (int sub = 0; sub < 2; sub++) {
                        int j = p * 2 + sub;
                        MMA16816(acc[i][j], ah[i], bh[sub*2], bh[sub*2+1]);
                        MMA16816(acc[i][j], ah[i], bl[sub*2], bl[sub*2+1]);
                        MMA16816(acc[i][j], al[i], bh[sub*2], bh[sub*2+1]);
                    }
            }
        }
        __syncthreads();
    }
    #pragma unroll
    for (int i = 0; i < 2; i++) {
        int row0 = m0 + wm*32 + i*16 + (lane >> 2);
        #pragma unroll
        for (int j = 0; j < 8; j++) {
            int col = n0 + wn*64 + (j >> 1)*16 + (j & 1)*8 + (lane & 3)*2;
            float2 b2 = *(const float2*)(bias + col);
            #pragma unroll
            for (int half = 0; half < 2; half++) {
                int r = row0 + half*8;
                size_t off = (size_t)r * M + col;
                float2 r2 = *(const float2*)(res + off);
                float2 o = {acc[i][j][half*2+0] + b2.x + r2.x,
                            acc[i][j][half*2+1] + b2.y + r2.y};
                *(float2*)(C + off) = o;
            }
        }
    }
}

// ---------------- fused flash attention (unchanged from R10) ----------------
#define FTSTR 72
#define FQ_H 0
#define FQ_L 18432
#define FKV0 36864
#define FKV_STAGE 36864
#define FK_H 0
#define FK_L 9216
#define FV_H 18432
#define FV_L 27648
#define F_SMEM (FKV0 + 2*FKV_STAGE)

#define F_LOADKV(kt, stg) do {                                            \
    uint32_t base_ = sb + FKV0 + (uint32_t)(stg) * FKV_STAGE;             \
    _Pragma("unroll")                                                     \
    for (int u = 0; u < 2; u++) {                                         \
        int idx = tid + u * 256;                                          \
        int r = idx >> 3, c = (idx & 7) * 8;                              \
        size_t gk = (size_t)((kt) * 64 + r) * (2 * DD) + c;               \
        uint32_t so = (uint32_t)(r * FTSTR + c) * 2;                      \
        cp16(base_ + FK_H + so, kb_h + gk);                               \
        cp16(base_ + FK_L + so, kb_l + gk);                               \
        cp16(base_ + FV_H + so, kb_h + gk + DD);                          \
        cp16(base_ + FV_L + so, kb_l + gk + DD);                          \
    }                                                                     \
} while (0)

__global__ void __launch_bounds__(256) fattn_kernel(
    const __nv_bfloat16* __restrict__ Qh_, const __nv_bfloat16* __restrict__ Ql_,
    const __nv_bfloat16* __restrict__ KVh, const __nv_bfloat16* __restrict__ KVl,
    __nv_bfloat16* __restrict__ Ohi, __nv_bfloat16* __restrict__ Olo)
{
    extern __shared__ char smem[];
    uint32_t sb = smem_u32(smem);
    int tid = threadIdx.x, lane = tid & 31, w = tid >> 5;
    int qtile = gridDim.x - 1 - blockIdx.x;
    int bh = blockIdx.y;
    int b = bh >> 4, h = bh & 15;
    int q0 = qtile * 128;

    const __nv_bfloat16* kb_h = KVh + (size_t)b * SSEQ * 2 * DD + h * HD;
    const __nv_bfloat16* kb_l = KVl + (size_t)b * SSEQ * 2 * DD + h * HD;

    F_LOADKV(0, 0);
    CP_COMMIT();
    #pragma unroll
    for (int u = 0; u < 4; u++) {
        int idx = tid + u * 256;
        int r = idx >> 3, c = (idx & 7) * 8;
        size_t g = ((size_t)b * SSEQ + q0 + r) * DD + h * HD + c;
        uint32_t so = (uint32_t)(r * FTSTR + c) * 2;
        *(uint4*)(smem + FQ_H + so) = *(const uint4*)(Qh_ + g);
        *(uint4*)(smem + FQ_L + so) = *(const uint4*)(Ql_ + g);
    }
    __syncthreads();

    uint32_t qh[4][4], ql[4][4];
    uint32_t a_off = (uint32_t)((w * 16 + (lane & 15)) * FTSTR + ((lane >> 4) << 3)) * 2;
    #pragma unroll
    for (int ks = 0; ks < 4; ks++) {
        LDMX4(qh[ks][0], qh[ks][1], qh[ks][2], qh[ks][3], sb + FQ_H + a_off + ks * 32);
        LDMX4(ql[ks][0], ql[ks][1], ql[ks][2], ql[ks][3], sb + FQ_L + a_off + ks * 32);
    }

    float m0 = -1e30f, m1 = -1e30f, l0 = 0.0f, l1 = 0.0f;
    float o[8][4];
    #pragma unroll
    for (int j = 0; j < 8; j++)
        #pragma unroll
        for (int c = 0; c < 4; c++) o[j][c] = 0.0f;

    float slope = exp2f(-0.5f * (float)(h + 1));
    int row0 = q0 + w * 16 + (lane >> 2);
    int warp_rmax = q0 + w * 16 + 15;
    int nkt = (q0 + 127) / 64 + 1;

    for (int kt = 0; kt < nkt; kt++) {
        if (kt + 1 < nkt) { F_LOADKV(kt + 1, (kt + 1) & 1); CP_COMMIT(); CP_WAIT1(); }
        else             { CP_WAIT0(); }
        __syncthreads();
        uint32_t stb = sb + FKV0 + (uint32_t)(kt & 1) * FKV_STAGE;

        if (kt * 64 <= warp_rmax) {
            float S[8][4];
            #pragma unroll
            for (int j = 0; j < 8; j++)
                #pragma unroll
                for (int c = 0; c < 4; c++) S[j][c] = 0.0f;
            #pragma unroll
            for (int ks = 0; ks < 4; ks++) {
                #pragma unroll
                for (int p = 0; p < 4; p++) {
                    uint32_t kh[4], kl[4];
                    uint32_t boff = (uint32_t)((p * 16 + ((lane >> 4) << 3) + (lane & 7)) * FTSTR
                                               + (((lane >> 3) & 1) << 3)) * 2 + ks * 32;
                    LDMX4(kh[0], kh[1], kh[2], kh[3], stb + FK_H + boff);
                    LDMX4(kl[0], kl[1], kl[2], kl[3], stb + FK_L + boff);
                    MMA16816(S[p*2+0], qh[ks], kh[0], kh[1]);
                    MMA16816(S[p*2+1], qh[ks], kh[2], kh[3]);
                    MMA16816(S[p*2+0], qh[ks], kl[0], kl[1]);
                    MMA16816(S[p*2+1], qh[ks], kl[2], kl[3]);
                    MMA16816(S[p*2+0], ql[ks], kh[0], kh[1]);
                    MMA16816(S[p*2+1], ql[ks], kh[2], kh[3]);
                }
            }
            #pragma unroll
            for (int j = 0; j < 8; j++) {
                int col = kt * 64 + j * 8 + (lane & 3) * 2;
                S[j][0] = (col     <= row0)     ? S[j][0] + slope*(float)(col     - row0)     : -1e30f;
                S[j][1] = (col + 1 <= row0)     ? S[j][1] + slope*(float)(col + 1 - row0)     : -1e30f;
                S[j][2] = (col     <= row0 + 8) ? S[j][2] + slope*(float)(col     - row0 - 8) : -1e30f;
                S[j][3] = (col + 1 <= row0 + 8) ? S[j][3] + slope*(float)(col + 1 - row0 - 8) : -1e30f;
            }
            float rm0 = -1e30f, rm1 = -1e30f;
            #pragma unroll
            for (int j = 0; j < 8; j++) {
                rm0 = fmaxf(rm0, fmaxf(S[j][0], S[j][1]));
                rm1 = fmaxf(rm1, fmaxf(S[j][2], S[j][3]));
            }
            rm0 = fmaxf(rm0, __shfl_xor_sync(0xffffffffu, rm0, 1));
            rm0 = fmaxf(rm0, __shfl_xor_sync(0xffffffffu, rm0, 2));
            rm1 = fmaxf(rm1, __shfl_xor_sync(0xffffffffu, rm1, 1));
            rm1 = fmaxf(rm1, __shfl_xor_sync(0xffffffffu, rm1, 2));
            float mn0 = fmaxf(m0, rm0), mn1 = fmaxf(m1, rm1);
            float al0 = expf(m0 - mn0), al1 = expf(m1 - mn1);
            m0 = mn0; m1 = mn1;
            float ps0 = 0.0f, ps1 = 0.0f;
            #pragma unroll
            for (int j = 0; j < 8; j++) {
                S[j][0] = expf(S[j][0] - m0); S[j][1] = expf(S[j][1] - m0);
                S[j][2] = expf(S[j][2] - m1); S[j][3] = expf(S[j][3] - m1);
                ps0 += S[j][0] + S[j][1];
                ps1 += S[j][2] + S[j][3];
            }
            l0 = l0 * al0 + ps0;
            l1 = l1 * al1 + ps1;
            #pragma unroll
            for (int j = 0; j < 8; j++) {
                o[j][0] *= al0; o[j][1] *= al0;
                o[j][2] *= al1; o[j][3] *= al1;
            }
            #pragma unroll
            for (int j = 0; j < 4; j++) {
                uint32_t ph[4], pl[4];
                split2(S[2*j  ][0], S[2*j  ][1], ph[0], pl[0]);
                split2(S[2*j  ][2], S[2*j  ][3], ph[1], pl[1]);
                split2(S[2*j+1][0], S[2*j+1][1], ph[2], pl[2]);
                split2(S[2*j+1][2], S[2*j+1][3], ph[3], pl[3]);
                #pragma unroll
                for (int pp = 0; pp < 4; pp++) {
                    uint32_t vh[4], vl[4];
                    uint32_t voff = (uint32_t)((j*16 + (lane & 15)) * FTSTR
                                               + pp*16 + ((lane >> 4) << 3)) * 2;
                    LDMX4T(vh[0], vh[1], vh[2], vh[3], stb + FV_H + voff);
                    LDMX4T(vl[0], vl[1], vl[2], vl[3], stb + FV_L + voff);
                    MMA16816(o[pp*2+0], ph, vh[0], vh[1]);
                    MMA16816(o[pp*2+1], ph, vh[2], vh[3]);
                    MMA16816(o[pp*2+0], ph, vl[0], vl[1]);
                    MMA16816(o[pp*2+1], ph, vl[2], vl[3]);
                    MMA16816(o[pp*2+0], pl, vh[0], vh[1]);
                    MMA16816(o[pp*2+1], pl, vh[2], vh[3]);
                }
            }
        }
        __syncthreads();
    }

    l0 += __shfl_xor_sync(0xffffffffu, l0, 1);
    l0 += __shfl_xor_sync(0xffffffffu, l0, 2);
    l1 += __shfl_xor_sync(0xffffffffu, l1, 1);
    l1 += __shfl_xor_sync(0xffffffffu, l1, 2);
    float i0 = 1.0f / l0, i1 = 1.0f / l1;

    size_t gr0 = (size_t)b * SSEQ + q0 + w * 16 + (lane >> 2);
    #pragma unroll
    for (int j = 0; j < 8; j++) {
        int col = h * HD + j * 8 + (lane & 3) * 2;
        uint32_t uh, ul;
        split2(o[j][0] * i0, o[j][1] * i0, uh, ul);
        *(uint32_t*)(Ohi + gr0 * DD + col) = uh;
        *(uint32_t*)(Olo + gr0 * DD + col) = ul;
        split2(o[j][2] * i1, o[j][3] * i1, uh, ul);
        *(uint32_t*)(Ohi + (gr0 + 8) * DD + col) = uh;
        *(uint32_t*)(Olo + (gr0 + 8) * DD + col) = ul;
    }
}

// ---------------- host ----------------
extern "C" void kernel_launch(void* const* d_in, const int* in_sizes, int n_in,
                              void* d_out, int out_size)
{
    const float *ts, *fg, *fb, *wq, *bq, *wkv, *bkv, *wo, *bo,
                *w1, *b1, *w2, *b2, *ag, *ab, *ffg, *ffb;
    if (in_sizes[1] == 1024) {
        ts  = (const float*)d_in[0];
        fg  = (const float*)d_in[1];  fb  = (const float*)d_in[2];
        wq  = (const float*)d_in[3];  bq  = (const float*)d_in[4];
        wkv = (const float*)d_in[5];  bkv = (const float*)d_in[6];
        wo  = (const float*)d_in[7];  bo  = (const float*)d_in[8];
        w1  = (const float*)d_in[9];  b1  = (const float*)d_in[10];
        w2  = (const float*)d_in[11]; b2  = (const float*)d_in[12];
        ag  = (const float*)d_in[13]; ab  = (const float*)d_in[14];
        ffg = (const float*)d_in[15]; ffb = (const float*)d_in[16];
    } else {
        ts  = (const float*)d_in[0];
        wq  = (const float*)d_in[1];  bq  = (const float*)d_in[2];
        wkv = (const float*)d_in[3];  bkv = (const float*)d_in[4];
        wo  = (const float*)d_in[5];  bo  = (const float*)d_in[6];
        w1  = (const float*)d_in[7];  b1  = (const float*)d_in[8];
        w2  = (const float*)d_in[9];  b2  = (const float*)d_in[10];
        ag  = (const float*)d_in[11]; ab  = (const float*)d_in[12];
        ffg = (const float*)d_in[13]; ffb = (const float*)d_in[14];
        fg  = (const float*)d_in[15]; fb  = (const float*)d_in[16];
    }

    float *x, *F, *sh, *sf, *swqkv, *sw1, *sw2;
    unsigned *fmax, *mxqkv, *mxw1, *mxw2;
    int8_t *h8h, *h8l, *f8h, *f8l, *wqkv8h, *wqkv8l, *w18h, *w18l, *w28h, *w28l;
    __nv_bfloat16 *qh_, *ql_, *kvh, *kvl, *ath, *atl, *woh, *wol;
    cudaGetSymbolAddress((void**)&x,    g_x);
    cudaGetSymbolAddress((void**)&F,    g_f);
    cudaGetSymbolAddress((void**)&fmax, g_fmax);
    cudaGetSymbolAddress((void**)&h8h,  g_h8h);
    cudaGetSymbolAddress((void**)&h8l,  g_h8l);
    cudaGetSymbolAddress((void**)&sh,   g_sh);
    cudaGetSymbolAddress((void**)&f8h,  g_f8h);
    cudaGetSymbolAddress((void**)&f8l,  g_f8l);
    cudaGetSymbolAddress((void**)&sf,   g_sf);
    cudaGetSymbolAddress((void**)&qh_,  g_q_hi);
    cudaGetSymbolAddress((void**)&ql_,  g_q_lo);
    cudaGetSymbolAddress((void**)&kvh,  g_kv_hi);
    cudaGetSymbolAddress((void**)&kvl,  g_kv_lo);
    cudaGetSymbolAddress((void**)&ath,  g_att_hi);
    cudaGetSymbolAddress((void**)&atl,  g_att_lo);
    cudaGetSymbolAddress((void**)&wqkv8h, g_wqkv8h);
    cudaGetSymbolAddress((void**)&wqkv8l, g_wqkv8l);
    cudaGetSymbolAddress((void**)&swqkv,  g_swqkv);
    cudaGetSymbolAddress((void**)&mxqkv,  g_mxqkv);
    cudaGetSymbolAddress((void**)&w18h, g_w18h);
    cudaGetSymbolAddress((void**)&w18l, g_w18l);
    cudaGetSymbolAddress((void**)&sw1,  g_sw1);
    cudaGetSymbolAddress((void**)&mxw1, g_mxw1);
    cudaGetSymbolAddress((void**)&w28h, g_w28h);
    cudaGetSymbolAddress((void**)&w28l, g_w28l);
    cudaGetSymbolAddress((void**)&sw2,  g_sw2);
    cudaGetSymbolAddress((void**)&mxw2, g_mxw2);
    cudaGetSymbolAddress((void**)&woh,  g_wo_h);
    cudaGetSymbolAddress((void**)&wol,  g_wo_l);

    cudaFuncSetAttribute(tgemm_q8,
                         cudaFuncAttributeMaxDynamicSharedMemorySize, Q_SMEM);
    cudaFuncSetAttribute(tgemm_bf16,
                         cudaFuncAttributeMaxDynamicSharedMemorySize, TG_SMEM);
    cudaFuncSetAttribute(fattn_kernel,
                         cudaFuncAttributeMaxDynamicSharedMemorySize, F_SMEM);

    cudaMemcpyAsync(x, ts, sizeof(float)*(size_t)NT*DD, cudaMemcpyDeviceToDevice, 0);

    // ---- weight pipeline: max -> finalize -> quant-transpose ----
    {
        dim3 blk(32, 8);
        wq8max_kernel<<<dim3(DD/256, 8, NL), 256>>>(wq,  mxqkv,      DD, DD,   3*DD);
        wq8max_kernel<<<dim3(2*DD/256, 8, NL), 256>>>(wkv, mxqkv+DD, DD, 2*DD, 3*DD);
        wq8max_kernel<<<dim3(FF/256, 8, NL), 256>>>(w1,  mxw1, DD, FF, FF);
        wq8max_kernel<<<dim3(DD/256, 8, NL), 256>>>(w2,  mxw2, FF, DD, DD);
        wq8fin_kernel<<<(NL*3*DD)/256, 256>>>(mxqkv, swqkv, NL*3*DD);
        wq8fin_kernel<<<(NL*FF)/256,  256>>>(mxw1, sw1, NL*FF);
        wq8fin_kernel<<<(NL*DD)/256,  256>>>(mxw2, sw2, NL*DD);
        wq8conv_kernel<<<dim3(DD/32, DD/32, NL), blk>>>(
            wq, wqkv8h, wqkv8l, swqkv, DD, DD, (size_t)3*DD*DD, 3*DD);
        wq8conv_kernel<<<dim3(2*DD/32, DD/32, NL), blk>>>(
            wkv, wqkv8h + DD*DD, wqkv8l + DD*DD, swqkv + DD, DD, 2*DD, (size_t)3*DD*DD, 3*DD);
        wq8conv_kernel<<<dim3(FF/32, DD/32, NL), blk>>>(
            w1, w18h, w18l, sw1, DD, FF, (size_t)DD*FF, FF);
        wq8conv_kernel<<<dim3(DD/32, FF/32, NL), blk>>>(
            w2, w28h, w28l, sw2, FF, DD, (size_t)FF*DD, DD);
        wconv_kernel<<<dim3(DD/32, DD/32, NL), blk>>>(wo, woh, wol, DD, DD);
    }

    for (int l = 0; l < NL; l++) {
        ln_q8_kernel<<<NT, 256>>>(x, ag + (size_t)l*DD, ab + (size_t)l*DD, h8h, h8l, sh);
        tgemm_q8<<<dim3(3*DD/64, NT/128), 256, Q_SMEM>>>(
            h8h, h8l, wqkv8h + (size_t)l*3*DD*DD, wqkv8l + (size_t)l*3*DD*DD,
            sh, swqkv + (size_t)l*3*DD,
            bq + (size_t)l*DD, bkv + (size_t)l*2*DD, nullptr, nullptr,
            qh_, ql_, kvh, kvl, nullptr, nullptr, DD, 3*DD, 4);
        fattn_kernel<<<dim3(SSEQ/128, BB*HH), 256, F_SMEM>>>(
            qh_, ql_, kvh, kvl, ath, atl);
        tgemm_bf16<<<dim3(DD/128, NT/128), 256, TG_SMEM>>>(
            ath, atl, woh + (size_t)l*DD*DD, wol + (size_t)l*DD*DD,
            bo + (size_t)l*DD, x, x, DD, DD);
        ln_q8_kernel<<<NT, 256>>>(x, ffg + (size_t)l*DD, ffb + (size_t)l*DD, h8h, h8l, sh);
        cudaMemsetAsync(fmax, 0, NT * sizeof(unsigned), 0);
        tgemm_q8<<<dim3(FF/64, NT/128), 256, Q_SMEM>>>(
            h8h, h8l, w18h + (size_t)l*DD*FF, w18l + (size_t)l*DD*FF,
            sh, sw1 + (size_t)l*FF,
            b1 + (size_t)l*FF, nullptr, nullptr, nullptr,
            nullptr, nullptr, nullptr, nullptr, F, fmax, DD, FF, 1);
        fquant_kernel<<<NT, 256>>>(F, fmax, f8h, f8l, sf);
        tgemm_q8<<<dim3(DD/64, NT/128), 256, Q_SMEM>>>(
            f8h, f8l, w28h + (size_t)l*FF*DD, w28l + (size_t)l*FF*DD,
            sf, sw2 + (size_t)l*DD,
            b2 + (size_t)l*DD, nullptr, x, x,
            nullptr, nullptr, nullptr, nullptr, nullptr, nullptr, FF, DD, 2);
    }

    ln_kernel<<<NT, 256>>>(x, fg, fb, (float*)d_out);
}

// round 14
// speedup vs baseline: 2.0125x; 2.0125x over previous
#include <cuda_runtime.h>
#include <cuda_bf16.h>
#include <math.h>
#include <stdint.h>

#define BB 2
#define SSEQ 2048
#define DD 1024
#define HH 16
#define HD 64
#define FF 4096
#define NL 8
#define NT (BB*SSEQ)

// ---------------- scratch ----------------
__device__ float g_x[NT*DD];
__device__ __nv_bfloat16 g_h_hi[NT*DD];
__device__ __nv_bfloat16 g_h_lo[NT*DD];
__device__ __nv_bfloat16 g_q_hi[NT*DD];
__device__ __nv_bfloat16 g_q_lo[NT*DD];
__device__ __nv_bfloat16 g_kv_hi[NT*2*DD];
__device__ __nv_bfloat16 g_kv_lo[NT*2*DD];
__device__ __nv_bfloat16 g_att_hi[NT*DD];
__device__ __nv_bfloat16 g_att_lo[NT*DD];
__device__ __nv_bfloat16 g_f_hi[NT*FF];
__device__ __nv_bfloat16 g_f_lo[NT*FF];
__device__ __nv_bfloat16 g_wqkv_h[NL*3*DD*DD];
__device__ __nv_bfloat16 g_wqkv_l[NL*3*DD*DD];
__device__ __nv_bfloat16 g_wo_h[NL*DD*DD];
__device__ __nv_bfloat16 g_wo_l[NL*DD*DD];
__device__ __nv_bfloat16 g_w1_h[NL*DD*FF];
__device__ __nv_bfloat16 g_w1_l[NL*DD*FF];
__device__ __nv_bfloat16 g_w2_h[NL*FF*DD];
__device__ __nv_bfloat16 g_w2_l[NL*FF*DD];

// ---------------- helpers ----------------
__device__ __forceinline__ float softplus_f(float x) {
    return fmaxf(x, 0.0f) + log1pf(expf(-fabsf(x)));
}
__device__ __forceinline__ uint32_t smem_u32(const void* p) {
    uint32_t a;
    asm("{ .reg .u64 t; cvta.to.shared.u64 t, %1; cvt.u32.u64 %0, t; }" : "=r"(a) : "l"(p));
    return a;
}
__device__ __forceinline__ void cp16(uint32_t s, const void* g) {
    asm volatile("cp.async.cg.shared.global [%0], [%1], 16;" :: "r"(s), "l"(g));
}
#define CP_COMMIT() asm volatile("cp.async.commit_group;")
#define CP_WAIT0()  asm volatile("cp.async.wait_group 0;")
#define CP_WAIT1()  asm volatile("cp.async.wait_group 1;")
__device__ __forceinline__ void split2(float a, float b, uint32_t& hi, uint32_t& lo) {
    __nv_bfloat162 h = __floats2bfloat162_rn(a, b);
    float ra = a - __bfloat162float(h.x);
    float rb = b - __bfloat162float(h.y);
    __nv_bfloat162 l = __floats2bfloat162_rn(ra, rb);
    hi = *(uint32_t*)&h; lo = *(uint32_t*)&l;
}
#define LDMX4(R0,R1,R2,R3,ADDR) \
    asm volatile("ldmatrix.sync.aligned.m8n8.x4.shared.b16 {%0,%1,%2,%3}, [%4];" \
        : "=r"(R0),"=r"(R1),"=r"(R2),"=r"(R3) : "r"(ADDR))
#define LDMX4T(R0,R1,R2,R3,ADDR) \
    asm volatile("ldmatrix.sync.aligned.m8n8.x4.trans.shared.b16 {%0,%1,%2,%3}, [%4];" \
        : "=r"(R0),"=r"(R1),"=r"(R2),"=r"(R3) : "r"(ADDR))
#define MMA16816(C, A, B0, B1) \
    asm volatile("mma.sync.aligned.m16n8k16.row.col.f32.bf16.bf16.f32 " \
        "{%0,%1,%2,%3}, {%4,%5,%6,%7}, {%8,%9}, {%0,%1,%2,%3};" \
        : "+f"((C)[0]),"+f"((C)[1]),"+f"((C)[2]),"+f"((C)[3]) \
        : "r"((A)[0]),"r"((A)[1]),"r"((A)[2]),"r"((A)[3]), "r"(B0),"r"(B1))

// ---------------- weight transpose + split ----------------
__global__ void wconv_kernel(const float* __restrict__ W,
                             __nv_bfloat16* __restrict__ oh,
                             __nv_bfloat16* __restrict__ ol,
                             int K, int M, size_t ostride)
{
    W  += (size_t)blockIdx.z * K * M;
    oh += (size_t)blockIdx.z * ostride;
    ol += (size_t)blockIdx.z * ostride;
    __shared__ float t[32][33];
    int m0 = blockIdx.x * 32, k0 = blockIdx.y * 32;
    int tx = threadIdx.x, ty = threadIdx.y;
    #pragma unroll
    for (int j = 0; j < 4; j++)
        t[ty + 8*j][tx] = W[(size_t)(k0 + ty + 8*j) * M + m0 + tx];
    __syncthreads();
    #pragma unroll
    for (int j = 0; j < 4; j++) {
        float v = t[tx][ty + 8*j];
        int m = m0 + ty + 8*j, k = k0 + tx;
        __nv_bfloat16 h = __float2bfloat16(v);
        oh[(size_t)m * K + k] = h;
        ol[(size_t)m * K + k] = __float2bfloat16(v - __bfloat162float(h));
    }
}

// ---------------- LayerNorms ----------------
#define LN_REDUCE() \
    _Pragma("unroll") \
    for (int o = 16; o > 0; o >>= 1) { \
        s  += __shfl_xor_sync(0xffffffffu, s,  o); \
        sq += __shfl_xor_sync(0xffffffffu, sq, o); } \
    if ((tid & 31) == 0) { sm1[tid >> 5] = s; sm2[tid >> 5] = sq; } \
    __syncthreads(); \
    if (tid < 32) { \
        s  = (tid < 8) ? sm1[tid] : 0.0f; \
        sq = (tid < 8) ? sm2[tid] : 0.0f; \
        _Pragma("unroll") \
        for (int o = 4; o > 0; o >>= 1) { \
            s  += __shfl_xor_sync(0xffffffffu, s,  o); \
            sq += __shfl_xor_sync(0xffffffffu, sq, o); } \
        if (tid == 0) { sm1[0] = s; sm2[0] = sq; } } \
    __syncthreads();

__global__ void ln_kernel(const float* __restrict__ in, const float* __restrict__ gamma,
                          const float* __restrict__ beta, float* __restrict__ out)
{
    int row = blockIdx.x, tid = threadIdx.x;
    float4 v = *(const float4*)(in + (size_t)row * DD + tid * 4);
    float s  = v.x + v.y + v.z + v.w;
    float sq = v.x*v.x + v.y*v.y + v.z*v.z + v.w*v.w;
    __shared__ float sm1[8], sm2[8];
    LN_REDUCE();
    float mean = sm1[0] * (1.0f / DD);
    float var  = sm2[0] * (1.0f / DD) - mean * mean;
    float rs   = rsqrtf(var + 1e-3f);
    float4 g  = *(const float4*)(gamma + tid * 4);
    float4 be = *(const float4*)(beta  + tid * 4);
    float4 o4;
    o4.x = (v.x - mean) * rs * g.x + be.x;
    o4.y = (v.y - mean) * rs * g.y + be.y;
    o4.z = (v.z - mean) * rs * g.z + be.z;
    o4.w = (v.w - mean) * rs * g.w + be.w;
    *(float4*)(out + (size_t)row * DD + tid * 4) = o4;
}

__global__ void ln_bf16_kernel(const float* __restrict__ in, const float* __restrict__ gamma,
                               const float* __restrict__ beta,
                               __nv_bfloat16* __restrict__ ohi, __nv_bfloat16* __restrict__ olo)
{
    int row = blockIdx.x, tid = threadIdx.x;
    float4 v = *(const float4*)(in + (size_t)row * DD + tid * 4);
    float s  = v.x + v.y + v.z + v.w;
    float sq = v.x*v.x + v.y*v.y + v.z*v.z + v.w*v.w;
    __shared__ float sm1[8], sm2[8];
    LN_REDUCE();
    float mean = sm1[0] * (1.0f / DD);
    float var  = sm2[0] * (1.0f / DD) - mean * mean;
    float rs   = rsqrtf(var + 1e-3f);
    float4 g  = *(const float4*)(gamma + tid * 4);
    float4 be = *(const float4*)(beta  + tid * 4);
    float a = (v.x - mean) * rs * g.x + be.x;
    float b = (v.y - mean) * rs * g.y + be.y;
    float c = (v.z - mean) * rs * g.z + be.z;
    float d = (v.w - mean) * rs * g.w + be.w;
    uint2 uh, ul;
    split2(a, b, uh.x, ul.x);
    split2(c, d, uh.y, ul.y);
    size_t off = (size_t)row * DD + tid * 4;
    *(uint2*)(ohi + off) = uh;
    *(uint2*)(olo + off) = ul;
}

// ---------------- HMMA split-bf16 GEMM, 128x128, cp.async 2-stage -----------
// Pass-scheduled MMAs: 3 product passes over 16 accumulators (no acc RAW chains)
#define TSTR 72
#define SA_H 0
#define SA_L 18432
#define SB_H 36864
#define SB_L 55296
#define TG_STAGE 73728
#define TG_SMEM (2*TG_STAGE)

#define TG_LOADS(kb, stg) do {                                            \
    uint32_t base_ = sb + (uint32_t)(stg) * TG_STAGE;                     \
    _Pragma("unroll")                                                     \
    for (int u = 0; u < 4; u++) {                                         \
        int idx = tid + u * 256;                                          \
        int r = idx >> 3, c = (idx & 7) * 8;                              \
        size_t g = (size_t)(m0 + r) * K + (kb) + c;                       \
        uint32_t so = (uint32_t)(r * TSTR + c) * 2;                       \
        cp16(base_ + SA_H + so, Ah + g);                                  \
        cp16(base_ + SA_L + so, Al + g);                                  \
        size_t gb = (size_t)(n0 + r) * K + (kb) + c;                      \
        cp16(base_ + SB_H + so, Bh + gb);                                 \
        cp16(base_ + SB_L + so, Bl + gb);                                 \
    }                                                                     \
} while (0)

__global__ void __launch_bounds__(256) tgemm_kernel(
    const __nv_bfloat16* __restrict__ Ah, const __nv_bfloat16* __restrict__ Al,
    const __nv_bfloat16* __restrict__ Bh, const __nv_bfloat16* __restrict__ Bl,
    const float* __restrict__ bias, const float* __restrict__ bias2,
    const float* __restrict__ res,
    float* __restrict__ C, __nv_bfloat16* __restrict__ Chi,
    __nv_bfloat16* __restrict__ Clo, __nv_bfloat16* __restrict__ Chi2,
    __nv_bfloat16* __restrict__ Clo2, int K, int M, int epi)
{
    extern __shared__ char smem[];
    uint32_t sb = smem_u32(smem);
    int tid = threadIdx.x, lane = tid & 31, w = tid >> 5;
    int wm = w & 3, wn = w >> 2;
    int m0 = blockIdx.y * 128, n0 = blockIdx.x * 128;

    float acc[2][8][4];
    #pragma unroll
    for (int i = 0; i < 2; i++)
        #pragma unroll
        for (int j = 0; j < 8; j++)
            #pragma unroll
            for (int c = 0; c < 4; c++) acc[i][j][c] = 0.0f;

    uint32_t a_off = (uint32_t)((wm*32 + (lane & 15))*TSTR + ((lane >> 4) << 3)) * 2;
    uint32_t b_off = (uint32_t)((wn*64 + ((lane >> 4) << 3) + (lane & 7))*TSTR
                                + (((lane >> 3) & 1) << 3)) * 2;

    int nch = K >> 6;
    TG_LOADS(0, 0);
    CP_COMMIT();

    for (int kc = 0; kc < nch; kc++) {
        if (kc + 1 < nch) { TG_LOADS((kc + 1)*64, (kc + 1) & 1); CP_COMMIT(); CP_WAIT1(); }
        else             { CP_WAIT0(); }
        __syncthreads();

        uint32_t stb = sb + (uint32_t)(kc & 1) * TG_STAGE;
        #pragma unroll
        for (int ks = 0; ks < 4; ks++) {
            uint32_t kb = (uint32_t)(ks * 16) * 2;
            uint32_t ah[2][4], al[2][4], bh[4][4], bl[4][4];
            #pragma unroll
            for (int i = 0; i < 2; i++) {
                uint32_t aa = stb + SA_H + a_off + (uint32_t)(i*16*TSTR)*2 + kb;
                LDMX4(ah[i][0], ah[i][1], ah[i][2], ah[i][3], aa);
                LDMX4(al[i][0], al[i][1], al[i][2], al[i][3], aa + (SA_L - SA_H));
            }
            #pragma unroll
            for (int p = 0; p < 4; p++) {
                uint32_t ba = stb + SB_H + b_off + (uint32_t)(p*16*TSTR)*2 + kb;
                LDMX4(bh[p][0], bh[p][1], bh[p][2], bh[p][3], ba);
                LDMX4(bl[p][0], bl[p][1], bl[p][2], bl[p][3], ba + (SB_L - SB_H));
            }
            // pass 1: hi*hi — 16 distinct accumulators back-to-back
            #pragma unroll
            for (int i = 0; i < 2; i++)
                #pragma unroll
                for (int p = 0; p < 4; p++)
                    #pragma unroll
                    for (int sub = 0; sub < 2; sub++)
                        MMA16816(acc[i][p*2+sub], ah[i], bh[p][sub*2], bh[p][sub*2+1]);
            // pass 2: hi*lo
            #pragma unroll
            for (int i = 0; i < 2; i++)
                #pragma unroll
                for (int p = 0; p < 4; p++)
                    #pragma unroll
                    for (int sub = 0; sub < 2; sub++)
                        MMA16816(acc[i][p*2+sub], ah[i], bl[p][sub*2], bl[p][sub*2+1]);
            // pass 3: lo*hi
            #pragma unroll
            for (int i = 0; i < 2; i++)
                #pragma unroll
                for (int p = 0; p < 4; p++)
                    #pragma unroll
                    for (int sub = 0; sub < 2; sub++)
                        MMA16816(acc[i][p*2+sub], al[i], bh[p][sub*2], bh[p][sub*2+1]);
        }
        __syncthreads();
    }

    // ---- epilogue ----
    #pragma unroll
    for (int i = 0; i < 2; i++) {
        int row0 = m0 + wm*32 + i*16 + (lane >> 2);
        #pragma unroll
        for (int j = 0; j < 8; j++) {
            int col = n0 + wn*64 + (j >> 1)*16 + (j & 1)*8 + (lane & 3)*2;
            #pragma unroll
            for (int half = 0; half < 2; half++) {
                int r = row0 + half*8;
                float o0 = acc[i][j][half*2+0];
                float o1 = acc[i][j][half*2+1];
                if (epi == 4) {
                    uint32_t uh, ul;
                    if (col < DD) {
                        float2 b2 = *(const float2*)(bias + col);
                        o0 = (o0 + b2.x) * 0.125f;
                        o1 = (o1 + b2.y) * 0.125f;
                        split2(o0, o1, uh, ul);
                        size_t off = (size_t)r * DD + col;
                        *(uint32_t*)(Chi + off) = uh;
                        *(uint32_t*)(Clo + off) = ul;
                    } else {
                        float2 b2 = *(const float2*)(bias2 + (col - DD));
                        o0 += b2.x; o1 += b2.y;
                        split2(o0, o1, uh, ul);
                        size_t off = (size_t)r * (2*DD) + (col - DD);
                        *(uint32_t*)(Chi2 + off) = uh;
                        *(uint32_t*)(Clo2 + off) = ul;
                    }
                } else if (epi == 1) {
                    float2 b2 = *(const float2*)(bias + col);
                    o0 = softplus_f(o0 + b2.x);
                    o1 = softplus_f(o1 + b2.y);
                    uint32_t uh, ul;
                    split2(o0, o1, uh, ul);
                    size_t off = (size_t)r * M + col;
                    *(uint32_t*)(Chi + off) = uh;
                    *(uint32_t*)(Clo + off) = ul;
                } else {
                    float2 b2 = *(const float2*)(bias + col);
                    size_t off = (size_t)r * M + col;
                    float2 r2 = *(const float2*)(res + off);
                    float2 o = {o0 + b2.x + r2.x, o1 + b2.y + r2.y};
                    *(float2*)(C + off) = o;
                }
            }
        }
    }
}

// ---------------- fused flash attention, pass-scheduled MMAs ----------------
#define FTSTR 72
#define FQ_H 0
#define FQ_L 18432
#define FKV0 36864
#define FKV_STAGE 36864
#define FK_H 0
#define FK_L 9216
#define FV_H 18432
#define FV_L 27648
#define F_SMEM (FKV0 + 2*FKV_STAGE)

#define F_LOADKV(kt, stg) do {                                            \
    uint32_t base_ = sb + FKV0 + (uint32_t)(stg) * FKV_STAGE;             \
    _Pragma("unroll")                                                     \
    for (int u = 0; u < 2; u++) {                                         \
        int idx = tid + u * 256;                                          \
        int r = idx >> 3, c = (idx & 7) * 8;                              \
        size_t gk = (size_t)((kt) * 64 + r) * (2 * DD) + c;               \
        uint32_t so = (uint32_t)(r * FTSTR + c) * 2;                      \
        cp16(base_ + FK_H + so, kb_h + gk);                               \
        cp16(base_ + FK_L + so, kb_l + gk);                               \
        cp16(base_ + FV_H + so, kb_h + gk + DD);                          \
        cp16(base_ + FV_L + so, kb_l + gk + DD);                          \
    }                                                                     \
} while (0)

__global__ void __launch_bounds__(256) fattn_kernel(
    const __nv_bfloat16* __restrict__ Qh_, const __nv_bfloat16* __restrict__ Ql_,
    const __nv_bfloat16* __restrict__ KVh, const __nv_bfloat16* __restrict__ KVl,
    __nv_bfloat16* __restrict__ Ohi, __nv_bfloat16* __restrict__ Olo)
{
    extern __shared__ char smem[];
    uint32_t sb = smem_u32(smem);
    int tid = threadIdx.x, lane = tid & 31, w = tid >> 5;
    int qtile = gridDim.x - 1 - blockIdx.x;
    int bh = blockIdx.y;
    int b = bh >> 4, h = bh & 15;
    int q0 = qtile * 128;

    const __nv_bfloat16* kb_h = KVh + (size_t)b * SSEQ * 2 * DD + h * HD;
    const __nv_bfloat16* kb_l = KVl + (size_t)b * SSEQ * 2 * DD + h * HD;

    F_LOADKV(0, 0);
    CP_COMMIT();
    #pragma unroll
    for (int u = 0; u < 4; u++) {
        int idx = tid + u * 256;
        int r = idx >> 3, c = (idx & 7) * 8;
        size_t g = ((size_t)b * SSEQ + q0 + r) * DD + h * HD + c;
        uint32_t so = (uint32_t)(r * FTSTR + c) * 2;
        *(uint4*)(smem + FQ_H + so) = *(const uint4*)(Qh_ + g);
        *(uint4*)(smem + FQ_L + so) = *(const uint4*)(Ql_ + g);
    }
    __syncthreads();

    uint32_t qh[4][4], ql[4][4];
    uint32_t a_off = (uint32_t)((w * 16 + (lane & 15)) * FTSTR + ((lane >> 4) << 3)) * 2;
    #pragma unroll
    for (int ks = 0; ks < 4; ks++) {
        LDMX4(qh[ks][0], qh[ks][1], qh[ks][2], qh[ks][3], sb + FQ_H + a_off + ks * 32);
        LDMX4(ql[ks][0], ql[ks][1], ql[ks][2], ql[ks][3], sb + FQ_L + a_off + ks * 32);
    }

    float m0 = -1e30f, m1 = -1e30f, l0 = 0.0f, l1 = 0.0f;
    float o[8][4];
    #pragma unroll
    for (int j = 0; j < 8; j++)
        #pragma unroll
        for (int c = 0; c < 4; c++) o[j][c] = 0.0f;

    float slope = exp2f(-0.5f * (float)(h + 1));
    int row0 = q0 + w * 16 + (lane >> 2);
    int warp_rmax = q0 + w * 16 + 15;
    int nkt = (q0 + 127) / 64 + 1;

    for (int kt = 0; kt < nkt; kt++) {
        if (kt + 1 < nkt) { F_LOADKV(kt + 1, (kt + 1) & 1); CP_COMMIT(); CP_WAIT1(); }
        else             { CP_WAIT0(); }
        __syncthreads();
        uint32_t stb = sb + FKV0 + (uint32_t)(kt & 1) * FKV_STAGE;

        if (kt * 64 <= warp_rmax) {
            float S[8][4];
            #pragma unroll
            for (int j = 0; j < 8; j++)
                #pragma unroll
                for (int c = 0; c < 4; c++) S[j][c] = 0.0f;

            #pragma unroll
            for (int ks = 0; ks < 4; ks++) {
                uint32_t kh[4][4], kl[4][4];
                #pragma unroll
                for (int p = 0; p < 4; p++) {
                    uint32_t boff = (uint32_t)((p*16 + ((lane >> 4) << 3) + (lane & 7)) * FTSTR
                                               + (((lane >> 3) & 1) << 3)) * 2 + ks * 32;
                    LDMX4(kh[p][0], kh[p][1], kh[p][2], kh[p][3], stb + FK_H + boff);
                    LDMX4(kl[p][0], kl[p][1], kl[p][2], kl[p][3], stb + FK_L + boff);
                }
                // pass 1: qh*kh — 8 distinct accs
                #pragma unroll
                for (int p = 0; p < 4; p++) {
                    MMA16816(S[p*2+0], qh[ks], kh[p][0], kh[p][1]);
                    MMA16816(S[p*2+1], qh[ks], kh[p][2], kh[p][3]);
                }
                // pass 2: qh*kl
                #pragma unroll
                for (int p = 0; p < 4; p++) {
                    MMA16816(S[p*2+0], qh[ks], kl[p][0], kl[p][1]);
                    MMA16816(S[p*2+1], qh[ks], kl[p][2], kl[p][3]);
                }
                // pass 3: ql*kh
                #pragma unroll
                for (int p = 0; p < 4; p++) {
                    MMA16816(S[p*2+0], ql[ks], kh[p][0], kh[p][1]);
                    MMA16816(S[p*2+1], ql[ks], kh[p][2], kh[p][3]);
                }
            }

            #pragma unroll
            for (int j = 0; j < 8; j++) {
                int col = kt * 64 + j * 8 + (lane & 3) * 2;
                S[j][0] = (col     <= row0)     ? S[j][0] + slope*(float)(col     - row0)     : -1e30f;
                S[j][1] = (col + 1 <= row0)     ? S[j][1] + slope*(float)(col + 1 - row0)     : -1e30f;
                S[j][2] = (col     <= row0 + 8) ? S[j][2] + slope*(float)(col     - row0 - 8) : -1e30f;
                S[j][3] = (col + 1 <= row0 + 8) ? S[j][3] + slope*(float)(col + 1 - row0 - 8) : -1e30f;
            }
            float rm0 = -1e30f, rm1 = -1e30f;
            #pragma unroll
            for (int j = 0; j < 8; j++) {
                rm0 = fmaxf(rm0, fmaxf(S[j][0], S[j][1]));
                rm1 = fmaxf(rm1, fmaxf(S[j][2], S[j][3]));
            }
            rm0 = fmaxf(rm0, __shfl_xor_sync(0xffffffffu, rm0, 1));
            rm0 = fmaxf(rm0, __shfl_xor_sync(0xffffffffu, rm0, 2));
            rm1 = fmaxf(rm1, __shfl_xor_sync(0xffffffffu, rm1, 1));
            rm1 = fmaxf(rm1, __shfl_xor_sync(0xffffffffu, rm1, 2));
            float mn0 = fmaxf(m0, rm0), mn1 = fmaxf(m1, rm1);
            float al0 = expf(m0 - mn0), al1 = expf(m1 - mn1);
            m0 = mn0; m1 = mn1;
            float ps0 = 0.0f, ps1 = 0.0f;
            #pragma unroll
            for (int j = 0; j < 8; j++) {
                S[j][0] = expf(S[j][0] - m0); S[j][1] = expf(S[j][1] - m0);
                S[j][2] = expf(S[j][2] - m1); S[j][3] = expf(S[j][3] - m1);
                ps0 += S[j][0] + S[j][1];
                ps1 += S[j][2] + S[j][3];
            }
            l0 = l0 * al0 + ps0;
            l1 = l1 * al1 + ps1;
            #pragma unroll
            for (int j = 0; j < 8; j++) {
                o[j][0] *= al0; o[j][1] *= al0;
                o[j][2] *= al1; o[j][3] *= al1;
            }

            #pragma unroll
            for (int j = 0; j < 4; j++) {
                uint32_t ph[4], pl[4];
                split2(S[2*j  ][0], S[2*j  ][1], ph[0], pl[0]);
                split2(S[2*j  ][2], S[2*j  ][3], ph[1], pl[1]);
                split2(S[2*j+1][0], S[2*j+1][1], ph[2], pl[2]);
                split2(S[2*j+1][2], S[2*j+1][3], ph[3], pl[3]);
                uint32_t vh[4][4], vl[4][4];
                #pragma unroll
                for (int pp = 0; pp < 4; pp++) {
                    uint32_t voff = (uint32_t)((j*16 + (lane & 15)) * FTSTR
                                               + pp*16 + ((lane >> 4) << 3)) * 2;
                    LDMX4T(vh[pp][0], vh[pp][1], vh[pp][2], vh[pp][3], stb + FV_H + voff);
                    LDMX4T(vl[pp][0], vl[pp][1], vl[pp][2], vl[pp][3], stb + FV_L + voff);
                }
                // pass 1: ph*vh — 8 distinct accs
                #pragma unroll
                for (int pp = 0; pp < 4; pp++) {
                    MMA16816(o[pp*2+0], ph, vh[pp][0], vh[pp][1]);
                    MMA16816(o[pp*2+1], ph, vh[pp][2], vh[pp][3]);
                }
                // pass 2: ph*vl
                #pragma unroll
                for (int pp = 0; pp < 4; pp++) {
                    MMA16816(o[pp*2+0], ph, vl[pp][0], vl[pp][1]);
                    MMA16816(o[pp*2+1], ph, vl[pp][2], vl[pp][3]);
                }
                // pass 3: pl*vh
                #pragma unroll
                for (int pp = 0; pp < 4; pp++) {
                    MMA16816(o[pp*2+0], pl, vh[pp][0], vh[pp][1]);
                    MMA16816(o[pp*2+1], pl, vh[pp][2], vh[pp][3]);
                }
            }
        }
        __syncthreads();
    }

    l0 += __shfl_xor_sync(0xffffffffu, l0, 1);
    l0 += __shfl_xor_sync(0xffffffffu, l0, 2);
    l1 += __shfl_xor_sync(0xffffffffu, l1, 1);
    l1 += __shfl_xor_sync(0xffffffffu, l1, 2);
    float i0 = 1.0f / l0, i1 = 1.0f / l1;

    size_t gr0 = (size_t)b * SSEQ + q0 + w * 16 + (lane >> 2);
    #pragma unroll
    for (int j = 0; j < 8; j++) {
        int col = h * HD + j * 8 + (lane & 3) * 2;
        uint32_t uh, ul;
        split2(o[j][0] * i0, o[j][1] * i0, uh, ul);
        *(uint32_t*)(Ohi + gr0 * DD + col) = uh;
        *(uint32_t*)(Olo + gr0 * DD + col) = ul;
        split2(o[j][2] * i1, o[j][3] * i1, uh, ul);
        *(uint32_t*)(Ohi + (gr0 + 8) * DD + col) = uh;
        *(uint32_t*)(Olo + (gr0 + 8) * DD + col) = ul;
    }
}

// ---------------- host ----------------
extern "C" void kernel_launch(void* const* d_in, const int* in_sizes, int n_in,
                              void* d_out, int out_size)
{
    const float *ts, *fg, *fb, *wq, *bq, *wkv, *bkv, *wo, *bo,
                *w1, *b1, *w2, *b2, *ag, *ab, *ffg, *ffb;
    if (in_sizes[1] == 1024) {
        ts  = (const float*)d_in[0];
        fg  = (const float*)d_in[1];  fb  = (const float*)d_in[2];
        wq  = (const float*)d_in[3];  bq  = (const float*)d_in[4];
        wkv = (const float*)d_in[5];  bkv = (const float*)d_in[6];
        wo  = (const float*)d_in[7];  bo  = (const float*)d_in[8];
        w1  = (const float*)d_in[9];  b1  = (const float*)d_in[10];
        w2  = (const float*)d_in[11]; b2  = (const float*)d_in[12];
        ag  = (const float*)d_in[13]; ab  = (const float*)d_in[14];
        ffg = (const float*)d_in[15]; ffb = (const float*)d_in[16];
    } else {
        ts  = (const float*)d_in[0];
        wq  = (const float*)d_in[1];  bq  = (const float*)d_in[2];
        wkv = (const float*)d_in[3];  bkv = (const float*)d_in[4];
        wo  = (const float*)d_in[5];  bo  = (const float*)d_in[6];
        w1  = (const float*)d_in[7];  b1  = (const float*)d_in[8];
        w2  = (const float*)d_in[9];  b2  = (const float*)d_in[10];
        ag  = (const float*)d_in[11]; ab  = (const float*)d_in[12];
        ffg = (const float*)d_in[13]; ffb = (const float*)d_in[14];
        fg  = (const float*)d_in[15]; fb  = (const float*)d_in[16];
    }

    float *x;
    __nv_bfloat16 *hh, *hl, *qh_, *ql_, *kvh, *kvl, *ath, *atl, *fh, *fl;
    __nv_bfloat16 *wqkvh, *wqkvl, *woh, *wol, *w1h, *w1l, *w2h, *w2l;
    cudaGetSymbolAddress((void**)&x,    g_x);
    cudaGetSymbolAddress((void**)&hh,   g_h_hi);
    cudaGetSymbolAddress((void**)&hl,   g_h_lo);
    cudaGetSymbolAddress((void**)&qh_,  g_q_hi);
    cudaGetSymbolAddress((void**)&ql_,  g_q_lo);
    cudaGetSymbolAddress((void**)&kvh,  g_kv_hi);
    cudaGetSymbolAddress((void**)&kvl,  g_kv_lo);
    cudaGetSymbolAddress((void**)&ath,  g_att_hi);
    cudaGetSymbolAddress((void**)&atl,  g_att_lo);
    cudaGetSymbolAddress((void**)&fh,   g_f_hi);
    cudaGetSymbolAddress((void**)&fl,   g_f_lo);
    cudaGetSymbolAddress((void**)&wqkvh, g_wqkv_h);
    cudaGetSymbolAddress((void**)&wqkvl, g_wqkv_l);
    cudaGetSymbolAddress((void**)&woh,  g_wo_h);
    cudaGetSymbolAddress((void**)&wol,  g_wo_l);
    cudaGetSymbolAddress((void**)&w1h,  g_w1_h);
    cudaGetSymbolAddress((void**)&w1l,  g_w1_l);
    cudaGetSymbolAddress((void**)&w2h,  g_w2_h);
    cudaGetSymbolAddress((void**)&w2l,  g_w2_l);

    cudaFuncSetAttribute(tgemm_kernel,
                         cudaFuncAttributeMaxDynamicSharedMemorySize, TG_SMEM);
    cudaFuncSetAttribute(fattn_kernel,
                         cudaFuncAttributeMaxDynamicSharedMemorySize, F_SMEM);

    cudaMemcpyAsync(x, ts, sizeof(float)*(size_t)NT*DD, cudaMemcpyDeviceToDevice, 0);

    {
        dim3 blk(32, 8);
        wconv_kernel<<<dim3(DD/32, DD/32, NL), blk>>>(
            wq,  wqkvh,         wqkvl,         DD, DD,   (size_t)3*DD*DD);
        wconv_kernel<<<dim3(2*DD/32, DD/32, NL), blk>>>(
            wkv, wqkvh + DD*DD, wqkvl + DD*DD, DD, 2*DD, (size_t)3*DD*DD);
        wconv_kernel<<<dim3(DD/32, DD/32, NL), blk>>>(
            wo,  woh,  wol,  DD, DD, (size_t)DD*DD);
        wconv_kernel<<<dim3(FF/32, DD/32, NL), blk>>>(
            w1,  w1h,  w1l,  DD, FF, (size_t)DD*FF);
        wconv_kernel<<<dim3(DD/32, FF/32, NL), blk>>>(
            w2,  w2h,  w2l,  FF, DD, (size_t)FF*DD);
    }

    for (int l = 0; l < NL; l++) {
        ln_bf16_kernel<<<NT, 256>>>(x, ag + (size_t)l*DD, ab + (size_t)l*DD, hh, hl);
        tgemm_kernel<<<dim3(3*DD/128, NT/128), 256, TG_SMEM>>>(
            hh, hl, wqkvh + (size_t)l*3*DD*DD, wqkvl + (size_t)l*3*DD*DD,
            bq + (size_t)l*DD, bkv + (size_t)l*2*DD, nullptr,
            nullptr, qh_, ql_, kvh, kvl, DD, 3*DD, 4);
        fattn_kernel<<<dim3(SSEQ/128, BB*HH), 256, F_SMEM>>>(
            qh_, ql_, kvh, kvl, ath, atl);
        tgemm_kernel<<<dim3(DD/128, NT/128), 256, TG_SMEM>>>(
            ath, atl, woh + (size_t)l*DD*DD, wol + (size_t)l*DD*DD,
            bo + (size_t)l*DD, nullptr, x,
            x, nullptr, nullptr, nullptr, nullptr, DD, DD, 2);
        ln_bf16_kernel<<<NT, 256>>>(x, ffg + (size_t)l*DD, ffb + (size_t)l*DD, hh, hl);
        tgemm_kernel<<<dim3(FF/128, NT/128), 256, TG_SMEM>>>(
            hh, hl, w1h + (size_t)l*DD*FF, w1l + (size_t)l*DD*FF,
            b1 + (size_t)l*FF, nullptr, nullptr,
            nullptr, fh, fl, nullptr, nullptr, DD, FF, 1);
        tgemm_kernel<<<dim3(DD/128, NT/128), 256, TG_SMEM>>>(
            fh, fl, w2h + (size_t)l*FF*DD, w2l + (size_t)l*FF*DD,
            b2 + (size_t)l*DD, nullptr, x,
            x, nullptr, nullptr, nullptr, nullptr, FF, DD, 2);
    }

    ln_kernel<<<NT, 256>>>(x, fg, fb, (float*)d_out);
}

// round 15
// speedup vs baseline: 2.0409x; 1.0141x over previous
#include <cuda_runtime.h>
#include <cuda_bf16.h>
#include <math.h>
#include <stdint.h>

#define BB 2
#define SSEQ 2048
#define DD 1024
#define HH 16
#define HD 64
#define FF 4096
#define NL 8
#define NT (BB*SSEQ)

// ---------------- scratch ----------------
__device__ float g_x[NT*DD];
__device__ __nv_bfloat16 g_h_hi[NT*DD];
__device__ __nv_bfloat16 g_h_lo[NT*DD];
__device__ __nv_bfloat16 g_q_hi[NT*DD];
__device__ __nv_bfloat16 g_q_lo[NT*DD];
__device__ __nv_bfloat16 g_kv_hi[NT*2*DD];
__device__ __nv_bfloat16 g_kv_lo[NT*2*DD];
__device__ __nv_bfloat16 g_att_hi[NT*DD];
__device__ __nv_bfloat16 g_att_lo[NT*DD];
__device__ __nv_bfloat16 g_f_hi[NT*FF];
__device__ __nv_bfloat16 g_f_lo[NT*FF];
__device__ __nv_bfloat16 g_wqkv_h[NL*3*DD*DD];
__device__ __nv_bfloat16 g_wqkv_l[NL*3*DD*DD];
__device__ __nv_bfloat16 g_wo_h[NL*DD*DD];
__device__ __nv_bfloat16 g_wo_l[NL*DD*DD];
__device__ __nv_bfloat16 g_w1_h[NL*DD*FF];
__device__ __nv_bfloat16 g_w1_l[NL*DD*FF];
__device__ __nv_bfloat16 g_w2_h[NL*FF*DD];
__device__ __nv_bfloat16 g_w2_l[NL*FF*DD];

// ---------------- helpers ----------------
__device__ __forceinline__ float softplus_f(float x) {
    return fmaxf(x, 0.0f) + log1pf(expf(-fabsf(x)));
}
__device__ __forceinline__ uint32_t smem_u32(const void* p) {
    uint32_t a;
    asm("{ .reg .u64 t; cvta.to.shared.u64 t, %1; cvt.u32.u64 %0, t; }" : "=r"(a) : "l"(p));
    return a;
}
__device__ __forceinline__ void cp16(uint32_t s, const void* g) {
    asm volatile("cp.async.cg.shared.global [%0], [%1], 16;" :: "r"(s), "l"(g));
}
#define CP_COMMIT() asm volatile("cp.async.commit_group;")
#define CP_WAIT0()  asm volatile("cp.async.wait_group 0;")
#define CP_WAIT1()  asm volatile("cp.async.wait_group 1;")
__device__ __forceinline__ void split2(float a, float b, uint32_t& hi, uint32_t& lo) {
    __nv_bfloat162 h = __floats2bfloat162_rn(a, b);
    float ra = a - __bfloat162float(h.x);
    float rb = b - __bfloat162float(h.y);
    __nv_bfloat162 l = __floats2bfloat162_rn(ra, rb);
    hi = *(uint32_t*)&h; lo = *(uint32_t*)&l;
}
#define LDMX4(R0,R1,R2,R3,ADDR) \
    asm volatile("ldmatrix.sync.aligned.m8n8.x4.shared.b16 {%0,%1,%2,%3}, [%4];" \
        : "=r"(R0),"=r"(R1),"=r"(R2),"=r"(R3) : "r"(ADDR))
#define LDMX4T(R0,R1,R2,R3,ADDR) \
    asm volatile("ldmatrix.sync.aligned.m8n8.x4.trans.shared.b16 {%0,%1,%2,%3}, [%4];" \
        : "=r"(R0),"=r"(R1),"=r"(R2),"=r"(R3) : "r"(ADDR))
#define MMA16816(C, A, B0, B1) \
    asm volatile("mma.sync.aligned.m16n8k16.row.col.f32.bf16.bf16.f32 " \
        "{%0,%1,%2,%3}, {%4,%5,%6,%7}, {%8,%9}, {%0,%1,%2,%3};" \
        : "+f"((C)[0]),"+f"((C)[1]),"+f"((C)[2]),"+f"((C)[3]) \
        : "r"((A)[0]),"r"((A)[1]),"r"((A)[2]),"r"((A)[3]), "r"(B0),"r"(B1))

// ---------------- weight transpose + split (shared body) --------------------
__device__ __forceinline__ void wconv_tile(const float* __restrict__ W,
                                           __nv_bfloat16* __restrict__ oh,
                                           __nv_bfloat16* __restrict__ ol,
                                           int K, int M, int m0, int k0)
{
    __shared__ float t[32][33];
    int tx = threadIdx.x, ty = threadIdx.y;   // 32 x 8
    #pragma unroll
    for (int j = 0; j < 4; j++)
        t[ty + 8*j][tx] = W[(size_t)(k0 + ty + 8*j) * M + m0 + tx];
    __syncthreads();
    #pragma unroll
    for (int j = 0; j < 4; j++) {
        float v = t[tx][ty + 8*j];
        int m = m0 + ty + 8*j, k = k0 + tx;
        __nv_bfloat16 h = __float2bfloat16(v);
        oh[(size_t)m * K + k] = h;
        ol[(size_t)m * K + k] = __float2bfloat16(v - __bfloat162float(h));
    }
}

// merged wq+wkv -> packed wqkv  (grid: x = 96 m-tiles, y = 32 k-tiles, z = layer)
__global__ void wconv_qkv_kernel(const float* __restrict__ wq,
                                 const float* __restrict__ wkv,
                                 __nv_bfloat16* __restrict__ oh,
                                 __nv_bfloat16* __restrict__ ol)
{
    int l = blockIdx.z;
    oh += (size_t)l * 3 * DD * DD;
    ol += (size_t)l * 3 * DD * DD;
    int bx = blockIdx.x, k0 = blockIdx.y * 32;
    if (bx < 32) {
        wconv_tile(wq + (size_t)l * DD * DD, oh, ol, DD, DD, bx * 32, k0);
    } else {
        // wkv tile -> dest rows offset by DD
        wconv_tile(wkv + (size_t)l * DD * 2 * DD, oh + (size_t)DD * DD,
                   ol + (size_t)DD * DD, DD, 2 * DD, (bx - 32) * 32, k0);
    }
}

// wo  (grid: 32 x 32 x NL)
__global__ void wconv_wo_kernel(const float* __restrict__ wo,
                                __nv_bfloat16* __restrict__ oh,
                                __nv_bfloat16* __restrict__ ol)
{
    int l = blockIdx.z;
    wconv_tile(wo + (size_t)l * DD * DD, oh + (size_t)l * DD * DD,
               ol + (size_t)l * DD * DD, DD, DD, blockIdx.x * 32, blockIdx.y * 32);
}

// merged w1+w2  (grid: x = 4096 flat tiles, z in [0,16): z<8 -> w1 layer z, else w2)
__global__ void wconv_w12_kernel(const float* __restrict__ w1,
                                 const float* __restrict__ w2,
                                 __nv_bfloat16* __restrict__ w1h,
                                 __nv_bfloat16* __restrict__ w1l,
                                 __nv_bfloat16* __restrict__ w2h,
                                 __nv_bfloat16* __restrict__ w2l)
{
    int z = blockIdx.z, bx = blockIdx.x;
    if (z < NL) {
        // w1: [DD, FF] -> 128 m-tiles x 32 k-tiles
        int mt = bx & 127, kt = bx >> 7;
        size_t off = (size_t)z * DD * FF;
        wconv_tile(w1 + off, w1h + off, w1l + off, DD, FF, mt * 32, kt * 32);
    } else {
        // w2: [FF, DD] -> 32 m-tiles x 128 k-tiles
        int mt = bx & 31, kt = bx >> 5;
        size_t off = (size_t)(z - NL) * FF * DD;
        wconv_tile(w2 + off, w2h + off, w2l + off, FF, DD, mt * 32, kt * 32);
    }
}

// ---------------- LayerNorms ----------------
#define LN_REDUCE() \
    _Pragma("unroll") \
    for (int o = 16; o > 0; o >>= 1) { \
        s  += __shfl_xor_sync(0xffffffffu, s,  o); \
        sq += __shfl_xor_sync(0xffffffffu, sq, o); } \
    if ((tid & 31) == 0) { sm1[tid >> 5] = s; sm2[tid >> 5] = sq; } \
    __syncthreads(); \
    if (tid < 32) { \
        s  = (tid < 8) ? sm1[tid] : 0.0f; \
        sq = (tid < 8) ? sm2[tid] : 0.0f; \
        _Pragma("unroll") \
        for (int o = 4; o > 0; o >>= 1) { \
            s  += __shfl_xor_sync(0xffffffffu, s,  o); \
            sq += __shfl_xor_sync(0xffffffffu, sq, o); } \
        if (tid == 0) { sm1[0] = s; sm2[0] = sq; } } \
    __syncthreads();

__global__ void ln_kernel(const float* __restrict__ in, const float* __restrict__ gamma,
                          const float* __restrict__ beta, float* __restrict__ out)
{
    int row = blockIdx.x, tid = threadIdx.x;
    float4 v = *(const float4*)(in + (size_t)row * DD + tid * 4);
    float s  = v.x + v.y + v.z + v.w;
    float sq = v.x*v.x + v.y*v.y + v.z*v.z + v.w*v.w;
    __shared__ float sm1[8], sm2[8];
    LN_REDUCE();
    float mean = sm1[0] * (1.0f / DD);
    float var  = sm2[0] * (1.0f / DD) - mean * mean;
    float rs   = rsqrtf(var + 1e-3f);
    float4 g  = *(const float4*)(gamma + tid * 4);
    float4 be = *(const float4*)(beta  + tid * 4);
    float4 o4;
    o4.x = (v.x - mean) * rs * g.x + be.x;
    o4.y = (v.y - mean) * rs * g.y + be.y;
    o4.z = (v.z - mean) * rs * g.z + be.z;
    o4.w = (v.w - mean) * rs * g.w + be.w;
    *(float4*)(out + (size_t)row * DD + tid * 4) = o4;
}

__global__ void ln_bf16_kernel(const float* __restrict__ in, const float* __restrict__ gamma,
                               const float* __restrict__ beta,
                               __nv_bfloat16* __restrict__ ohi, __nv_bfloat16* __restrict__ olo)
{
    int row = blockIdx.x, tid = threadIdx.x;
    float4 v = *(const float4*)(in + (size_t)row * DD + tid * 4);
    float s  = v.x + v.y + v.z + v.w;
    float sq = v.x*v.x + v.y*v.y + v.z*v.z + v.w*v.w;
    __shared__ float sm1[8], sm2[8];
    LN_REDUCE();
    float mean = sm1[0] * (1.0f / DD);
    float var  = sm2[0] * (1.0f / DD) - mean * mean;
    float rs   = rsqrtf(var + 1e-3f);
    float4 g  = *(const float4*)(gamma + tid * 4);
    float4 be = *(const float4*)(beta  + tid * 4);
    float a = (v.x - mean) * rs * g.x + be.x;
    float b = (v.y - mean) * rs * g.y + be.y;
    float c = (v.z - mean) * rs * g.z + be.z;
    float d = (v.w - mean) * rs * g.w + be.w;
    uint2 uh, ul;
    split2(a, b, uh.x, ul.x);
    split2(c, d, uh.y, ul.y);
    size_t off = (size_t)row * DD + tid * 4;
    *(uint2*)(ohi + off) = uh;
    *(uint2*)(olo + off) = ul;
}

// ---------------- HMMA split-bf16 GEMM, 128x128, cp.async 2-stage (R10) -----
#define TSTR 72
#define SA_H 0
#define SA_L 18432
#define SB_H 36864
#define SB_L 55296
#define TG_STAGE 73728
#define TG_SMEM (2*TG_STAGE)

#define TG_LOADS(kb, stg) do {                                            \
    uint32_t base_ = sb + (uint32_t)(stg) * TG_STAGE;                     \
    _Pragma("unroll")                                                     \
    for (int u = 0; u < 4; u++) {                                         \
        int idx = tid + u * 256;                                          \
        int r = idx >> 3, c = (idx & 7) * 8;                              \
        size_t g = (size_t)(m0 + r) * K + (kb) + c;                       \
        uint32_t so = (uint32_t)(r * TSTR + c) * 2;                       \
        cp16(base_ + SA_H + so, Ah + g);                                  \
        cp16(base_ + SA_L + so, Al + g);                                  \
        size_t gb = (size_t)(n0 + r) * K + (kb) + c;                      \
        cp16(base_ + SB_H + so, Bh + gb);                                 \
        cp16(base_ + SB_L + so, Bl + gb);                                 \
    }                                                                     \
} while (0)

__global__ void __launch_bounds__(256) tgemm_kernel(
    const __nv_bfloat16* __restrict__ Ah, const __nv_bfloat16* __restrict__ Al,
    const __nv_bfloat16* __restrict__ Bh, const __nv_bfloat16* __restrict__ Bl,
    const float* __restrict__ bias, const float* __restrict__ bias2,
    const float* __restrict__ res,
    float* __restrict__ C, __nv_bfloat16* __restrict__ Chi,
    __nv_bfloat16* __restrict__ Clo, __nv_bfloat16* __restrict__ Chi2,
    __nv_bfloat16* __restrict__ Clo2, int K, int M, int epi)
{
    extern __shared__ char smem[];
    uint32_t sb = smem_u32(smem);
    int tid = threadIdx.x, lane = tid & 31, w = tid >> 5;
    int wm = w & 3, wn = w >> 2;
    int m0 = blockIdx.y * 128, n0 = blockIdx.x * 128;

    float acc[2][8][4];
    #pragma unroll
    for (int i = 0; i < 2; i++)
        #pragma unroll
        for (int j = 0; j < 8; j++)
            #pragma unroll
            for (int c = 0; c < 4; c++) acc[i][j][c] = 0.0f;

    uint32_t a_off = (uint32_t)((wm*32 + (lane & 15))*TSTR + ((lane >> 4) << 3)) * 2;
    uint32_t b_off = (uint32_t)((wn*64 + ((lane >> 4) << 3) + (lane & 7))*TSTR
                                + (((lane >> 3) & 1) << 3)) * 2;

    int nch = K >> 6;
    TG_LOADS(0, 0);
    CP_COMMIT();

    for (int kc = 0; kc < nch; kc++) {
        if (kc + 1 < nch) { TG_LOADS((kc + 1)*64, (kc + 1) & 1); CP_COMMIT(); CP_WAIT1(); }
        else             { CP_WAIT0(); }
        __syncthreads();

        uint32_t stb = sb + (uint32_t)(kc & 1) * TG_STAGE;
        #pragma unroll
        for (int ks = 0; ks < 4; ks++) {
            uint32_t kb = (uint32_t)(ks * 16) * 2;
            uint32_t ah[2][4], al[2][4];
            #pragma unroll
            for (int i = 0; i < 2; i++) {
                uint32_t aa = stb + SA_H + a_off + (uint32_t)(i*16*TSTR)*2 + kb;
                LDMX4(ah[i][0], ah[i][1], ah[i][2], ah[i][3], aa);
                LDMX4(al[i][0], al[i][1], al[i][2], al[i][3], aa + (SA_L - SA_H));
            }
            #pragma unroll
            for (int p = 0; p < 4; p++) {
                uint32_t bh[4], bl[4];
                uint32_t ba = stb + SB_H + b_off + (uint32_t)(p*16*TSTR)*2 + kb;
                LDMX4(bh[0], bh[1], bh[2], bh[3], ba);
                LDMX4(bl[0], bl[1], bl[2], bl[3], ba + (SB_L - SB_H));
                #pragma unroll
                for (int i = 0; i < 2; i++)
                    #pragma unroll
                    for (int sub = 0; sub < 2; sub++) {
                        int j = p * 2 + sub;
                        MMA16816(acc[i][j], ah[i], bh[sub*2], bh[sub*2+1]);
                        MMA16816(acc[i][j], ah[i], bl[sub*2], bl[sub*2+1]);
                        MMA16816(acc[i][j], al[i], bh[sub*2], bh[sub*2+1]);
                    }
            }
        }
        __syncthreads();
    }

    // ---- epilogue ----
    #pragma unroll
    for (int i = 0; i < 2; i++) {
        int row0 = m0 + wm*32 + i*16 + (lane >> 2);
        #pragma unroll
        for (int j = 0; j < 8; j++) {
            int col = n0 + wn*64 + (j >> 1)*16 + (j & 1)*8 + (lane & 3)*2;
            #pragma unroll
            for (int half = 0; half < 2; half++) {
                int r = row0 + half*8;
                float o0 = acc[i][j][half*2+0];
                float o1 = acc[i][j][half*2+1];
                if (epi == 4) {
                    uint32_t uh, ul;
                    if (col < DD) {
                        float2 b2 = *(const float2*)(bias + col);
                        o0 = (o0 + b2.x) * 0.125f;
                        o1 = (o1 + b2.y) * 0.125f;
                        split2(o0, o1, uh, ul);
                        size_t off = (size_t)r * DD + col;
                        *(uint32_t*)(Chi + off) = uh;
                        *(uint32_t*)(Clo + off) = ul;
                    } else {
                        float2 b2 = *(const float2*)(bias2 + (col - DD));
                        o0 += b2.x; o1 += b2.y;
                        split2(o0, o1, uh, ul);
                        size_t off = (size_t)r * (2*DD) + (col - DD);
                        *(uint32_t*)(Chi2 + off) = uh;
                        *(uint32_t*)(Clo2 + off) = ul;
                    }
                } else if (epi == 1) {
                    float2 b2 = *(const float2*)(bias + col);
                    o0 = softplus_f(o0 + b2.x);
                    o1 = softplus_f(o1 + b2.y);
                    uint32_t uh, ul;
                    split2(o0, o1, uh, ul);
                    size_t off = (size_t)r * M + col;
                    *(uint32_t*)(Chi + off) = uh;
                    *(uint32_t*)(Clo + off) = ul;
                } else {
                    float2 b2 = *(const float2*)(bias + col);
                    size_t off = (size_t)r * M + col;
                    float2 r2 = *(const float2*)(res + off);
                    float2 o = {o0 + b2.x + r2.x, o1 + b2.y + r2.y};
                    *(float2*)(C + off) = o;
                }
            }
        }
    }
}

// ---------------- fused flash attention (R10) ----------------
#define FTSTR 72
#define FQ_H 0
#define FQ_L 18432
#define FKV0 36864
#define FKV_STAGE 36864
#define FK_H 0
#define FK_L 9216
#define FV_H 18432
#define FV_L 27648
#define F_SMEM (FKV0 + 2*FKV_STAGE)

#define F_LOADKV(kt, stg) do {                                            \
    uint32_t base_ = sb + FKV0 + (uint32_t)(stg) * FKV_STAGE;             \
    _Pragma("unroll")                                                     \
    for (int u = 0; u < 2; u++) {                                         \
        int idx = tid + u * 256;                                          \
        int r = idx >> 3, c = (idx & 7) * 8;                              \
        size_t gk = (size_t)((kt) * 64 + r) * (2 * DD) + c;               \
        uint32_t so = (uint32_t)(r * FTSTR + c) * 2;                      \
        cp16(base_ + FK_H + so, kb_h + gk);                               \
        cp16(base_ + FK_L + so, kb_l + gk);                               \
        cp16(base_ + FV_H + so, kb_h + gk + DD);                          \
        cp16(base_ + FV_L + so, kb_l + gk + DD);                          \
    }                                                                     \
} while (0)

__global__ void __launch_bounds__(256) fattn_kernel(
    const __nv_bfloat16* __restrict__ Qh_, const __nv_bfloat16* __restrict__ Ql_,
    const __nv_bfloat16* __restrict__ KVh, const __nv_bfloat16* __restrict__ KVl,
    __nv_bfloat16* __restrict__ Ohi, __nv_bfloat16* __restrict__ Olo)
{
    extern __shared__ char smem[];
    uint32_t sb = smem_u32(smem);
    int tid = threadIdx.x, lane = tid & 31, w = tid >> 5;
    int qtile = gridDim.x - 1 - blockIdx.x;
    int bh = blockIdx.y;
    int b = bh >> 4, h = bh & 15;
    int q0 = qtile * 128;

    const __nv_bfloat16* kb_h = KVh + (size_t)b * SSEQ * 2 * DD + h * HD;
    const __nv_bfloat16* kb_l = KVl + (size_t)b * SSEQ * 2 * DD + h * HD;

    F_LOADKV(0, 0);
    CP_COMMIT();
    #pragma unroll
    for (int u = 0; u < 4; u++) {
        int idx = tid + u * 256;
        int r = idx >> 3, c = (idx & 7) * 8;
        size_t g = ((size_t)b * SSEQ + q0 + r) * DD + h * HD + c;
        uint32_t so = (uint32_t)(r * FTSTR + c) * 2;
        *(uint4*)(smem + FQ_H + so) = *(const uint4*)(Qh_ + g);
        *(uint4*)(smem + FQ_L + so) = *(const uint4*)(Ql_ + g);
    }
    __syncthreads();

    uint32_t qh[4][4], ql[4][4];
    uint32_t a_off = (uint32_t)((w * 16 + (lane & 15)) * FTSTR + ((lane >> 4) << 3)) * 2;
    #pragma unroll
    for (int ks = 0; ks < 4; ks++) {
        LDMX4(qh[ks][0], qh[ks][1], qh[ks][2], qh[ks][3], sb + FQ_H + a_off + ks * 32);
        LDMX4(ql[ks][0], ql[ks][1], ql[ks][2], ql[ks][3], sb + FQ_L + a_off + ks * 32);
    }

    float m0 = -1e30f, m1 = -1e30f, l0 = 0.0f, l1 = 0.0f;
    float o[8][4];
    #pragma unroll
    for (int j = 0; j < 8; j++)
        #pragma unroll
        for (int c = 0; c < 4; c++) o[j][c] = 0.0f;

    float slope = exp2f(-0.5f * (float)(h + 1));
    int row0 = q0 + w * 16 + (lane >> 2);
    int warp_rmax = q0 + w * 16 + 15;
    int nkt = (q0 + 127) / 64 + 1;

    for (int kt = 0; kt < nkt; kt++) {
        if (kt + 1 < nkt) { F_LOADKV(kt + 1, (kt + 1) & 1); CP_COMMIT(); CP_WAIT1(); }
        else             { CP_WAIT0(); }
        __syncthreads();
        uint32_t stb = sb + FKV0 + (uint32_t)(kt & 1) * FKV_STAGE;

        if (kt * 64 <= warp_rmax) {
            float S[8][4];
            #pragma unroll
            for (int j = 0; j < 8; j++)
                #pragma unroll
                for (int c = 0; c < 4; c++) S[j][c] = 0.0f;
            #pragma unroll
            for (int ks = 0; ks < 4; ks++) {
                #pragma unroll
                for (int p = 0; p < 4; p++) {
                    uint32_t kh[4], kl[4];
                    uint32_t boff = (uint32_t)((p*16 + ((lane >> 4) << 3) + (lane & 7)) * FTSTR
                                               + (((lane >> 3) & 1) << 3)) * 2 + ks * 32;
                    LDMX4(kh[0], kh[1], kh[2], kh[3], stb + FK_H + boff);
                    LDMX4(kl[0], kl[1], kl[2], kl[3], stb + FK_L + boff);
                    MMA16816(S[p*2+0], qh[ks], kh[0], kh[1]);
                    MMA16816(S[p*2+1], qh[ks], kh[2], kh[3]);
                    MMA16816(S[p*2+0], qh[ks], kl[0], kl[1]);
                    MMA16816(S[p*2+1], qh[ks], kl[2], kl[3]);
                    MMA16816(S[p*2+0], ql[ks], kh[0], kh[1]);
                    MMA16816(S[p*2+1], ql[ks], kh[2], kh[3]);
                }
            }
            #pragma unroll
            for (int j = 0; j < 8; j++) {
                int col = kt * 64 + j * 8 + (lane & 3) * 2;
                S[j][0] = (col     <= row0)     ? S[j][0] + slope*(float)(col     - row0)     : -1e30f;
                S[j][1] = (col + 1 <= row0)     ? S[j][1] + slope*(float)(col + 1 - row0)     : -1e30f;
                S[j][2] = (col     <= row0 + 8) ? S[j][2] + slope*(float)(col     - row0 - 8) : -1e30f;
                S[j][3] = (col + 1 <= row0 + 8) ? S[j][3] + slope*(float)(col + 1 - row0 - 8) : -1e30f;
            }
            float rm0 = -1e30f, rm1 = -1e30f;
            #pragma unroll
            for (int j = 0; j < 8; j++) {
                rm0 = fmaxf(rm0, fmaxf(S[j][0], S[j][1]));
                rm1 = fmaxf(rm1, fmaxf(S[j][2], S[j][3]));
            }
            rm0 = fmaxf(rm0, __shfl_xor_sync(0xffffffffu, rm0, 1));
            rm0 = fmaxf(rm0, __shfl_xor_sync(0xffffffffu, rm0, 2));
            rm1 = fmaxf(rm1, __shfl_xor_sync(0xffffffffu, rm1, 1));
            rm1 = fmaxf(rm1, __shfl_xor_sync(0xffffffffu, rm1, 2));
            float mn0 = fmaxf(m0, rm0), mn1 = fmaxf(m1, rm1);
            float al0 = expf(m0 - mn0), al1 = expf(m1 - mn1);
            m0 = mn0; m1 = mn1;
            float ps0 = 0.0f, ps1 = 0.0f;
            #pragma unroll
            for (int j = 0; j < 8; j++) {
                S[j][0] = expf(S[j][0] - m0); S[j][1] = expf(S[j][1] - m0);
                S[j][2] = expf(S[j][2] - m1); S[j][3] = expf(S[j][3] - m1);
                ps0 += S[j][0] + S[j][1];
                ps1 += S[j][2] + S[j][3];
            }
            l0 = l0 * al0 + ps0;
            l1 = l1 * al1 + ps1;
            #pragma unroll
            for (int j = 0; j < 8; j++) {
                o[j][0] *= al0; o[j][1] *= al0;
                o[j][2] *= al1; o[j][3] *= al1;
            }
            #pragma unroll
            for (int j = 0; j < 4; j++) {
                uint32_t ph[4], pl[4];
                split2(S[2*j  ][0], S[2*j  ][1], ph[0], pl[0]);
                split2(S[2*j  ][2], S[2*j  ][3], ph[1], pl[1]);
                split2(S[2*j+1][0], S[2*j+1][1], ph[2], pl[2]);
                split2(S[2*j+1][2], S[2*j+1][3], ph[3], pl[3]);
                #pragma unroll
                for (int pp = 0; pp < 4; pp++) {
                    uint32_t vh[4], vl[4];
                    uint32_t voff = (uint32_t)((j*16 + (lane & 15)) * FTSTR
                                               + pp*16 + ((lane >> 4) << 3)) * 2;
                    LDMX4T(vh[0], vh[1], vh[2], vh[3], stb + FV_H + voff);
                    LDMX4T(vl[0], vl[1], vl[2], vl[3], stb + FV_L + voff);
                    MMA16816(o[pp*2+0], ph, vh[0], vh[1]);
                    MMA16816(o[pp*2+1], ph, vh[2], vh[3]);
                    MMA16816(o[pp*2+0], ph, vl[0], vl[1]);
                    MMA16816(o[pp*2+1], ph, vl[2], vl[3]);
                    MMA16816(o[pp*2+0], pl, vh[0], vh[1]);
                    MMA16816(o[pp*2+1], pl, vh[2], vh[3]);
                }
            }
        }
        __syncthreads();
    }

    l0 += __shfl_xor_sync(0xffffffffu, l0, 1);
    l0 += __shfl_xor_sync(0xffffffffu, l0, 2);
    l1 += __shfl_xor_sync(0xffffffffu, l1, 1);
    l1 += __shfl_xor_sync(0xffffffffu, l1, 2);
    float i0 = 1.0f / l0, i1 = 1.0f / l1;

    size_t gr0 = (size_t)b * SSEQ + q0 + w * 16 + (lane >> 2);
    #pragma unroll
    for (int j = 0; j < 8; j++) {
        int col = h * HD + j * 8 + (lane & 3) * 2;
        uint32_t uh, ul;
        split2(o[j][0] * i0, o[j][1] * i0, uh, ul);
        *(uint32_t*)(Ohi + gr0 * DD + col) = uh;
        *(uint32_t*)(Olo + gr0 * DD + col) = ul;
        split2(o[j][2] * i1, o[j][3] * i1, uh, ul);
        *(uint32_t*)(Ohi + (gr0 + 8) * DD + col) = uh;
        *(uint32_t*)(Olo + (gr0 + 8) * DD + col) = ul;
    }
}

// ---------------- host ----------------
extern "C" void kernel_launch(void* const* d_in, const int* in_sizes, int n_in,
                              void* d_out, int out_size)
{
    const float *ts, *fg, *fb, *wq, *bq, *wkv, *bkv, *wo, *bo,
                *w1, *b1, *w2, *b2, *ag, *ab, *ffg, *ffb;
    if (in_sizes[1] == 1024) {
        ts  = (const float*)d_in[0];
        fg  = (const float*)d_in[1];  fb  = (const float*)d_in[2];
        wq  = (const float*)d_in[3];  bq  = (const float*)d_in[4];
        wkv = (const float*)d_in[5];  bkv = (const float*)d_in[6];
        wo  = (const float*)d_in[7];  bo  = (const float*)d_in[8];
        w1  = (const float*)d_in[9];  b1  = (const float*)d_in[10];
        w2  = (const float*)d_in[11]; b2  = (const float*)d_in[12];
        ag  = (const float*)d_in[13]; ab  = (const float*)d_in[14];
        ffg = (const float*)d_in[15]; ffb = (const float*)d_in[16];
    } else {
        ts  = (const float*)d_in[0];
        wq  = (const float*)d_in[1];  bq  = (const float*)d_in[2];
        wkv = (const float*)d_in[3];  bkv = (const float*)d_in[4];
        wo  = (const float*)d_in[5];  bo  = (const float*)d_in[6];
        w1  = (const float*)d_in[7];  b1  = (const float*)d_in[8];
        w2  = (const float*)d_in[9];  b2  = (const float*)d_in[10];
        ag  = (const float*)d_in[11]; ab  = (const float*)d_in[12];
        ffg = (const float*)d_in[13]; ffb = (const float*)d_in[14];
        fg  = (const float*)d_in[15]; fb  = (const float*)d_in[16];
    }

    float *x;
    __nv_bfloat16 *hh, *hl, *qh_, *ql_, *kvh, *kvl, *ath, *atl, *fh, *fl;
    __nv_bfloat16 *wqkvh, *wqkvl, *woh, *wol, *w1h, *w1l, *w2h, *w2l;
    cudaGetSymbolAddress((void**)&x,    g_x);
    cudaGetSymbolAddress((void**)&hh,   g_h_hi);
    cudaGetSymbolAddress((void**)&hl,   g_h_lo);
    cudaGetSymbolAddress((void**)&qh_,  g_q_hi);
    cudaGetSymbolAddress((void**)&ql_,  g_q_lo);
    cudaGetSymbolAddress((void**)&kvh,  g_kv_hi);
    cudaGetSymbolAddress((void**)&kvl,  g_kv_lo);
    cudaGetSymbolAddress((void**)&ath,  g_att_hi);
    cudaGetSymbolAddress((void**)&atl,  g_att_lo);
    cudaGetSymbolAddress((void**)&fh,   g_f_hi);
    cudaGetSymbolAddress((void**)&fl,   g_f_lo);
    cudaGetSymbolAddress((void**)&wqkvh, g_wqkv_h);
    cudaGetSymbolAddress((void**)&wqkvl, g_wqkv_l);
    cudaGetSymbolAddress((void**)&woh,  g_wo_h);
    cudaGetSymbolAddress((void**)&wol,  g_wo_l);
    cudaGetSymbolAddress((void**)&w1h,  g_w1_h);
    cudaGetSymbolAddress((void**)&w1l,  g_w1_l);
    cudaGetSymbolAddress((void**)&w2h,  g_w2_h);
    cudaGetSymbolAddress((void**)&w2l,  g_w2_l);

    cudaFuncSetAttribute(tgemm_kernel,
                         cudaFuncAttributeMaxDynamicSharedMemorySize, TG_SMEM);
    cudaFuncSetAttribute(fattn_kernel,
                         cudaFuncAttributeMaxDynamicSharedMemorySize, F_SMEM);

    // launch #1 (memcpy kernel): residual init
    cudaMemcpyAsync(x, ts, sizeof(float)*(size_t)NT*DD, cudaMemcpyDeviceToDevice, 0);

    dim3 blk(32, 8);
    // launch #2: layer-0 pre-attention LN (independent of weight conversion)
    ln_bf16_kernel<<<NT, 256>>>(x, ag, ab, hh, hl);
    // launches #3-#5: merged weight conversions
    wconv_qkv_kernel<<<dim3(96, 32, NL), blk>>>(wq, wkv, wqkvh, wqkvl);
    wconv_wo_kernel<<<dim3(32, 32, NL), blk>>>(wo, woh, wol);
    wconv_w12_kernel<<<dim3(4096, 1, 2*NL), blk>>>(w1, w2, w1h, w1l, w2h, w2l);

    for (int l = 0; l < NL; l++) {
        if (l > 0)
            ln_bf16_kernel<<<NT, 256>>>(x, ag + (size_t)l*DD, ab + (size_t)l*DD, hh, hl);
        // launch #6 on first iteration = QKV tgemm -> captured by ncu
        tgemm_kernel<<<dim3(3*DD/128, NT/128), 256, TG_SMEM>>>(
            hh, hl, wqkvh + (size_t)l*3*DD*DD, wqkvl + (size_t)l*3*DD*DD,
            bq + (size_t)l*DD, bkv + (size_t)l*2*DD, nullptr,
            nullptr, qh_, ql_, kvh, kvl, DD, 3*DD, 4);
        fattn_kernel<<<dim3(SSEQ/128, BB*HH), 256, F_SMEM>>>(
            qh_, ql_, kvh, kvl, ath, atl);
        tgemm_kernel<<<dim3(DD/128, NT/128), 256, TG_SMEM>>>(
            ath, atl, woh + (size_t)l*DD*DD, wol + (size_t)l*DD*DD,
            bo + (size_t)l*DD, nullptr, x,
            x, nullptr, nullptr, nullptr, nullptr, DD, DD, 2);
        ln_bf16_kernel<<<NT, 256>>>(x, ffg + (size_t)l*DD, ffb + (size_t)l*DD, hh, hl);
        tgemm_kernel<<<dim3(FF/128, NT/128), 256, TG_SMEM>>>(
            hh, hl, w1h + (size_t)l*DD*FF, w1l + (size_t)l*DD*FF,
            b1 + (size_t)l*FF, nullptr, nullptr,
            nullptr, fh, fl, nullptr, nullptr, DD, FF, 1);
        tgemm_kernel<<<dim3(DD/128, NT/128), 256, TG_SMEM>>>(
            fh, fl, w2h + (size_t)l*FF*DD, w2l + (size_t)l*FF*DD,
            b2 + (size_t)l*DD, nullptr, x,
            x, nullptr, nullptr, nullptr, nullptr, FF, DD, 2);
    }

    ln_kernel<<<NT, 256>>>(x, fg, fb, (float*)d_out);
}